// round 2
// baseline (speedup 1.0000x reference)
#include <cuda_runtime.h>
#include <math.h>

// Problem constants
#define Bq   4
#define Tq   1024
#define Dq   1024
#define Hq   16
#define DHq  64
#define Mrows (Bq*Tq)          // 4096
#define OUT_ELEMS ((size_t)Mrows*Dq)              // 4,194,304
#define PROBS_ELEMS ((size_t)Bq*Hq*Tq*Tq)         // 67,108,864

// Scratch (device globals; no runtime allocation)
__device__ float g_lnq[Mrows*Dq];
__device__ float g_lnk[Mrows*Dq];
__device__ float g_lnv[Mrows*Dq];
__device__ float g_q[Mrows*Dq];
__device__ float g_k[Mrows*Dq];   // becomes kr = k + 0.1*r in-place
__device__ float g_v[Mrows*Dq];
__device__ float g_ctx[Mrows*Dq];

// ---------------------------------------------------------------------------
// LayerNorm over last dim (1024). One block per row, 256 threads, float4.
// ---------------------------------------------------------------------------
__global__ __launch_bounds__(256)
void ln_kernel(const float* __restrict__ x, const float* __restrict__ gamma,
               const float* __restrict__ beta, float* __restrict__ y)
{
    int row = blockIdx.x;
    int tid = threadIdx.x;
    const float4* xr = reinterpret_cast<const float4*>(x + (size_t)row * Dq);
    float4 v = xr[tid];
    float s  = v.x + v.y + v.z + v.w;
    float s2 = v.x*v.x + v.y*v.y + v.z*v.z + v.w*v.w;
    #pragma unroll
    for (int o = 16; o; o >>= 1) {
        s  += __shfl_xor_sync(0xffffffffu, s,  o);
        s2 += __shfl_xor_sync(0xffffffffu, s2, o);
    }
    __shared__ float ws[8], ws2[8], stats[2];
    int w = tid >> 5, lane = tid & 31;
    if (lane == 0) { ws[w] = s; ws2[w] = s2; }
    __syncthreads();
    if (tid == 0) {
        float ts = 0.f, ts2 = 0.f;
        #pragma unroll
        for (int i = 0; i < 8; i++) { ts += ws[i]; ts2 += ws2[i]; }
        float mu  = ts * (1.0f / Dq);
        float var = ts2 * (1.0f / Dq) - mu * mu;
        stats[0] = mu;
        stats[1] = rsqrtf(var + 1e-5f);
    }
    __syncthreads();
    float mu = stats[0], rstd = stats[1];
    float4 g = reinterpret_cast<const float4*>(gamma)[tid];
    float4 b = reinterpret_cast<const float4*>(beta)[tid];
    float4 o;
    o.x = (v.x - mu) * rstd * g.x + b.x;
    o.y = (v.y - mu) * rstd * g.y + b.y;
    o.z = (v.z - mu) * rstd * g.z + b.z;
    o.w = (v.w - mu) * rstd * g.w + b.w;
    reinterpret_cast<float4*>(y + (size_t)row * Dq)[tid] = o;
}

// ---------------------------------------------------------------------------
// SGEMM: C = alpha*(A@W + bias) + add      (bias/add optional)
// A: MxK row-major, W: KxN row-major. 128x128 tile, BK=8, 256 thr, 8x8/thread.
// ---------------------------------------------------------------------------
__global__ __launch_bounds__(256, 2)
void sgemm_kernel(const float* __restrict__ A, const float* __restrict__ W,
                  const float* __restrict__ bias, const float* __restrict__ add,
                  float alpha, float* __restrict__ C, int M, int N, int K)
{
    __shared__ float As[8][128];
    __shared__ float Bs[8][128];
    int bm = blockIdx.y * 128, bn = blockIdx.x * 128;
    int tid  = threadIdx.x;
    int arow = tid >> 1, acol = (tid & 1) * 4;
    int brow = tid >> 5, bcol = (tid & 31) * 4;
    const float* Aptr = A + (size_t)(bm + arow) * K + acol;
    const float* Wptr = W + (size_t)brow * N + bn + bcol;
    int tx = tid & 15, ty = tid >> 4;

    float acc[8][8];
    #pragma unroll
    for (int i = 0; i < 8; i++)
        #pragma unroll
        for (int j = 0; j < 8; j++) acc[i][j] = 0.f;

    float4 av = *(const float4*)Aptr;
    float4 bv = *(const float4*)Wptr;

    for (int k0 = 0; k0 < K; k0 += 8) {
        As[acol+0][arow] = av.x; As[acol+1][arow] = av.y;
        As[acol+2][arow] = av.z; As[acol+3][arow] = av.w;
        *(float4*)&Bs[brow][bcol] = bv;
        __syncthreads();
        if (k0 + 8 < K) {
            av = *(const float4*)(Aptr + k0 + 8);
            bv = *(const float4*)(Wptr + (size_t)(k0 + 8) * N);
        }
        #pragma unroll
        for (int k = 0; k < 8; k++) {
            float a[8], bf[8];
            *(float4*)&a[0]  = *(const float4*)&As[k][ty*8];
            *(float4*)&a[4]  = *(const float4*)&As[k][ty*8+4];
            *(float4*)&bf[0] = *(const float4*)&Bs[k][tx*8];
            *(float4*)&bf[4] = *(const float4*)&Bs[k][tx*8+4];
            #pragma unroll
            for (int i = 0; i < 8; i++)
                #pragma unroll
                for (int j = 0; j < 8; j++)
                    acc[i][j] += a[i] * bf[j];
        }
        __syncthreads();
    }

    float bb[8];
    #pragma unroll
    for (int j = 0; j < 8; j++) bb[j] = bias ? bias[bn + tx*8 + j] : 0.f;

    #pragma unroll
    for (int i = 0; i < 8; i++) {
        size_t roff = (size_t)(bm + ty*8 + i) * N + bn + tx*8;
        #pragma unroll
        for (int jj = 0; jj < 8; jj += 4) {
            float4 o;
            float v0 = (acc[i][jj+0] + bb[jj+0]) * alpha;
            float v1 = (acc[i][jj+1] + bb[jj+1]) * alpha;
            float v2 = (acc[i][jj+2] + bb[jj+2]) * alpha;
            float v3 = (acc[i][jj+3] + bb[jj+3]) * alpha;
            if (add) {
                float4 ad = *(const float4*)&add[roff + jj];
                v0 += ad.x; v1 += ad.y; v2 += ad.z; v3 += ad.w;
            }
            o.x = v0; o.y = v1; o.z = v2; o.w = v3;
            *(float4*)&C[roff + jj] = o;
        }
    }
}

// ---------------------------------------------------------------------------
// Attention: per block = (b, h, 32-query-row stripe).
//  phase1: scores = q @ kr^T (masked) -> smem stripe [32][1025]
//  softmax in smem, write probs to gmem
//  phase2: ctx = probs @ v
// ---------------------------------------------------------------------------
#define QT 32
#define SCS 1025             // padded score stride (conflict-free column reads)
#define KVS 68               // padded kv tile stride

__global__ __launch_bounds__(256)
void attn_kernel(const float* __restrict__ q, const float* __restrict__ kr,
                 const float* __restrict__ v, const int* __restrict__ mask,
                 float* __restrict__ probs, float* __restrict__ ctx)
{
    extern __shared__ float sm[];
    float* sc  = sm;                      // QT * SCS
    float* qT  = sc + QT * SCS;           // 64 * 33  (qT[d*33+m])
    float* kv  = qT + 64 * 33;            // 64 * KVS
    int*   msk = (int*)(kv + 64 * KVS);   // 1024

    int t0 = blockIdx.x * QT;
    int h  = blockIdx.y;
    int b  = blockIdx.z;
    int tid = threadIdx.x;
    int ty = tid >> 5, tx = tid & 31;

    // Load q stripe transposed: qT[d][m]
    {
        int m  = tid >> 3;
        int d0 = (tid & 7) * 8;
        const float* qp = q + ((size_t)(b*Tq + t0 + m) * Dq) + h*DHq + d0;
        float4 a = *(const float4*)qp;
        float4 c = *(const float4*)(qp + 4);
        qT[(d0+0)*33 + m] = a.x; qT[(d0+1)*33 + m] = a.y;
        qT[(d0+2)*33 + m] = a.z; qT[(d0+3)*33 + m] = a.w;
        qT[(d0+4)*33 + m] = c.x; qT[(d0+5)*33 + m] = c.y;
        qT[(d0+6)*33 + m] = c.z; qT[(d0+7)*33 + m] = c.w;
    }
    for (int s = tid; s < Tq; s += 256) msk[s] = mask[b*Tq + s];

    // ---------------- phase 1: scores ----------------
    for (int st = 0; st < Tq/64; st++) {
        int s0 = st * 64;
        {   // load kr tile transposed: kv[d*KVS + ss]
            int ss = tid >> 2;
            int d0 = (tid & 3) * 16;
            const float* kp = kr + ((size_t)(b*Tq + s0 + ss) * Dq) + h*DHq + d0;
            #pragma unroll
            for (int i = 0; i < 4; i++) {
                float4 a = *(const float4*)(kp + i*4);
                kv[(d0 + i*4 + 0)*KVS + ss] = a.x;
                kv[(d0 + i*4 + 1)*KVS + ss] = a.y;
                kv[(d0 + i*4 + 2)*KVS + ss] = a.z;
                kv[(d0 + i*4 + 3)*KVS + ss] = a.w;
            }
        }
        __syncthreads();

        float acc[4][2];
        #pragma unroll
        for (int i = 0; i < 4; i++) { acc[i][0] = 0.f; acc[i][1] = 0.f; }

        #pragma unroll 8
        for (int d = 0; d < 64; d++) {
            float b0 = kv[d*KVS + tx];
            float b1 = kv[d*KVS + tx + 32];
            #pragma unroll
            for (int i = 0; i < 4; i++) {
                float a = qT[d*33 + ty + 8*i];
                acc[i][0] += a * b0;
                acc[i][1] += a * b1;
            }
        }
        #pragma unroll
        for (int i = 0; i < 4; i++)
            #pragma unroll
            for (int j = 0; j < 2; j++) {
                int sn = s0 + tx + 32*j;
                float val = msk[sn] ? acc[i][j] : -1e9f;
                sc[(ty + 8*i)*SCS + sn] = val;
            }
        __syncthreads();
    }

    // ---------------- softmax (warp w owns rows 4w..4w+3) ----------------
    {
        int w = ty, lane = tx;
        #pragma unroll
        for (int rr = 0; rr < 4; rr++) {
            int r = w*4 + rr;
            float* row = sc + r*SCS;
            float vals[32];
            float mx = -3.4e38f;
            #pragma unroll
            for (int j = 0; j < 32; j++) {
                vals[j] = row[lane + 32*j];
                mx = fmaxf(mx, vals[j]);
            }
            #pragma unroll
            for (int o = 16; o; o >>= 1)
                mx = fmaxf(mx, __shfl_xor_sync(0xffffffffu, mx, o));
            float sum = 0.f;
            #pragma unroll
            for (int j = 0; j < 32; j++) {
                vals[j] = __expf(vals[j] - mx);
                sum += vals[j];
            }
            #pragma unroll
            for (int o = 16; o; o >>= 1)
                sum += __shfl_xor_sync(0xffffffffu, sum, o);
            float inv = 1.0f / sum;
            float* pout = probs + (((size_t)(b*Hq + h)*Tq) + t0 + r) * Tq;
            #pragma unroll
            for (int j = 0; j < 32; j++) {
                float p = vals[j] * inv;
                row[lane + 32*j]  = p;
                pout[lane + 32*j] = p;
            }
        }
    }
    __syncthreads();

    // ---------------- phase 2: ctx = probs @ v ----------------
    float oacc[4][2];
    #pragma unroll
    for (int i = 0; i < 4; i++) { oacc[i][0] = 0.f; oacc[i][1] = 0.f; }

    for (int st = 0; st < Tq/64; st++) {
        int s0 = st * 64;
        {   // load v tile natural: kv[ss*KVS + d]
            int ss = tid >> 2;
            int d0 = (tid & 3) * 16;
            const float* vp = v + ((size_t)(b*Tq + s0 + ss) * Dq) + h*DHq + d0;
            #pragma unroll
            for (int i = 0; i < 4; i++)
                *(float4*)&kv[ss*KVS + d0 + i*4] = *(const float4*)(vp + i*4);
        }
        __syncthreads();

        #pragma unroll 8
        for (int ss = 0; ss < 64; ss++) {
            float b0 = kv[ss*KVS + tx];
            float b1 = kv[ss*KVS + tx + 32];
            #pragma unroll
            for (int i = 0; i < 4; i++) {
                float a = sc[(ty + 8*i)*SCS + s0 + ss];
                oacc[i][0] += a * b0;
                oacc[i][1] += a * b1;
            }
        }
        __syncthreads();
    }

    #pragma unroll
    for (int i = 0; i < 4; i++)
        #pragma unroll
        for (int j = 0; j < 2; j++)
            ctx[((size_t)(b*Tq + t0 + ty + 8*i) * Dq) + h*DHq + tx + 32*j] = oacc[i][j];
}

// ---------------------------------------------------------------------------
extern "C" void kernel_launch(void* const* d_in, const int* in_sizes, int n_in,
                              void* d_out, int out_size)
{
    const float* query   = (const float*)d_in[0];
    const float* key     = (const float*)d_in[1];
    const float* value   = (const float*)d_in[2];
    const float* rel_pos = (const float*)d_in[3];
    const int*   kpm     = (const int*)  d_in[4];
    const float* qn_g = (const float*)d_in[5];
    const float* qn_b = (const float*)d_in[6];
    const float* kn_g = (const float*)d_in[7];
    const float* kn_b = (const float*)d_in[8];
    const float* vn_g = (const float*)d_in[9];
    const float* vn_b = (const float*)d_in[10];
    const float* Wq = (const float*)d_in[11];
    const float* bq = (const float*)d_in[12];
    const float* Wk = (const float*)d_in[13];
    const float* bk = (const float*)d_in[14];
    const float* Wv = (const float*)d_in[15];
    const float* bv = (const float*)d_in[16];
    const float* Wr = (const float*)d_in[17];
    const float* Wo = (const float*)d_in[18];
    const float* bo = (const float*)d_in[19];

    float* out   = (float*)d_out;
    float* probs = out + OUT_ELEMS;

    float *p_lnq, *p_lnk, *p_lnv, *p_q, *p_k, *p_v, *p_ctx;
    cudaGetSymbolAddress((void**)&p_lnq, g_lnq);
    cudaGetSymbolAddress((void**)&p_lnk, g_lnk);
    cudaGetSymbolAddress((void**)&p_lnv, g_lnv);
    cudaGetSymbolAddress((void**)&p_q,   g_q);
    cudaGetSymbolAddress((void**)&p_k,   g_k);
    cudaGetSymbolAddress((void**)&p_v,   g_v);
    cudaGetSymbolAddress((void**)&p_ctx, g_ctx);

    // attention smem
    int smem_bytes = (QT*SCS + 64*33 + 64*KVS) * (int)sizeof(float) + Tq * (int)sizeof(int);
    cudaFuncSetAttribute(attn_kernel, cudaFuncAttributeMaxDynamicSharedMemorySize, smem_bytes);

    // 1) LayerNorms
    ln_kernel<<<Mrows, 256>>>(query, qn_g, qn_b, p_lnq);
    ln_kernel<<<Mrows, 256>>>(key,   kn_g, kn_b, p_lnk);
    ln_kernel<<<Mrows, 256>>>(value, vn_g, vn_b, p_lnv);

    dim3 ggrid(Dq/128, Mrows/128);
    // 2) q = (ln(query)@Wq + bq) * 0.125
    sgemm_kernel<<<ggrid, 256>>>(p_lnq, Wq, bq, nullptr, 0.125f, p_q, Mrows, Dq, Dq);
    // 3) k = ln(key)@Wk + bk
    sgemm_kernel<<<ggrid, 256>>>(p_lnk, Wk, bk, nullptr, 1.0f, p_k, Mrows, Dq, Dq);
    // 4) v = ln(value)@Wv + bv
    sgemm_kernel<<<ggrid, 256>>>(p_lnv, Wv, bv, nullptr, 1.0f, p_v, Mrows, Dq, Dq);
    // 5) kr = k + 0.1*(rel_pos@Wr)   (in-place on g_k)
    sgemm_kernel<<<ggrid, 256>>>(rel_pos, Wr, nullptr, p_k, 0.1f, p_k, Mrows, Dq, Dq);

    // 6) attention -> probs (gmem) + ctx
    dim3 agrid(Tq/QT, Hq, Bq);
    attn_kernel<<<agrid, 256, smem_bytes>>>(p_q, p_k, p_v, kpm, probs, p_ctx);

    // 7) out = ctx@Wo + bo
    sgemm_kernel<<<ggrid, 256>>>(p_ctx, Wo, bo, nullptr, 1.0f, out, Mrows, Dq, Dq);
}

// round 3
// speedup vs baseline: 1.1474x; 1.1474x over previous
#include <cuda_runtime.h>
#include <math.h>

// Problem constants
#define Bq   4
#define Tq   1024
#define Dq   1024
#define Hq   16
#define DHq  64
#define Mrows (Bq*Tq)
#define OUT_ELEMS ((size_t)Mrows*Dq)

// Scratch (device globals; no runtime allocation)
__device__ float g_lnq[Mrows*Dq];
__device__ float g_lnk[Mrows*Dq];
__device__ float g_lnv[Mrows*Dq];
__device__ float g_q[Mrows*Dq];
__device__ float g_k[Mrows*Dq];   // becomes kr = k + 0.1*r in-place
__device__ float g_v[Mrows*Dq];
__device__ float g_ctx[Mrows*Dq];

// ------------------------- f32x2 packed helpers ----------------------------
__device__ __forceinline__ void fmaf2(unsigned long long &d,
                                      unsigned long long a,
                                      unsigned long long b) {
    asm("fma.rn.f32x2 %0, %1, %2, %0;" : "+l"(d) : "l"(a), "l"(b));
}
__device__ __forceinline__ unsigned long long pack2(float lo, float hi) {
    unsigned long long r;
    asm("mov.b64 %0, {%1, %2};" : "=l"(r) : "f"(lo), "f"(hi));
    return r;
}
__device__ __forceinline__ void unpack2(unsigned long long v, float &lo, float &hi) {
    asm("mov.b64 {%0, %1}, %2;" : "=f"(lo), "=f"(hi) : "l"(v));
}

// ---------------------------------------------------------------------------
// LayerNorm over last dim (1024). One block per row, 256 threads, float4.
// ---------------------------------------------------------------------------
__global__ __launch_bounds__(256)
void ln_kernel(const float* __restrict__ x, const float* __restrict__ gamma,
               const float* __restrict__ beta, float* __restrict__ y)
{
    int row = blockIdx.x;
    int tid = threadIdx.x;
    const float4* xr = reinterpret_cast<const float4*>(x + (size_t)row * Dq);
    float4 v = xr[tid];
    float s  = v.x + v.y + v.z + v.w;
    float s2 = v.x*v.x + v.y*v.y + v.z*v.z + v.w*v.w;
    #pragma unroll
    for (int o = 16; o; o >>= 1) {
        s  += __shfl_xor_sync(0xffffffffu, s,  o);
        s2 += __shfl_xor_sync(0xffffffffu, s2, o);
    }
    __shared__ float ws[8], ws2[8], stats[2];
    int w = tid >> 5, lane = tid & 31;
    if (lane == 0) { ws[w] = s; ws2[w] = s2; }
    __syncthreads();
    if (tid == 0) {
        float ts = 0.f, ts2 = 0.f;
        #pragma unroll
        for (int i = 0; i < 8; i++) { ts += ws[i]; ts2 += ws2[i]; }
        float mu  = ts * (1.0f / Dq);
        float var = ts2 * (1.0f / Dq) - mu * mu;
        stats[0] = mu;
        stats[1] = rsqrtf(var + 1e-5f);
    }
    __syncthreads();
    float mu = stats[0], rstd = stats[1];
    float4 g = reinterpret_cast<const float4*>(gamma)[tid];
    float4 b = reinterpret_cast<const float4*>(beta)[tid];
    float4 o;
    o.x = (v.x - mu) * rstd * g.x + b.x;
    o.y = (v.y - mu) * rstd * g.y + b.y;
    o.z = (v.z - mu) * rstd * g.z + b.z;
    o.w = (v.w - mu) * rstd * g.w + b.w;
    reinterpret_cast<float4*>(y + (size_t)row * Dq)[tid] = o;
}

// ---------------------------------------------------------------------------
// SGEMM: C = alpha*(A@W + bias) + add      (bias/add optional)
// 128x128 tile, BK=8, 256 thr, 8x8/thread, f32x2 packed FMA.
// ---------------------------------------------------------------------------
__global__ __launch_bounds__(256, 2)
void sgemm_kernel(const float* __restrict__ A, const float* __restrict__ W,
                  const float* __restrict__ bias, const float* __restrict__ add,
                  float alpha, float* __restrict__ C, int M, int N, int K)
{
    __shared__ float As[8][128];
    __shared__ float Bs[8][128];
    int bm = blockIdx.y * 128, bn = blockIdx.x * 128;
    int tid  = threadIdx.x;
    int arow = tid >> 1, acol = (tid & 1) * 4;
    int brow = tid >> 5, bcol = (tid & 31) * 4;
    const float* Aptr = A + (size_t)(bm + arow) * K + acol;
    const float* Wptr = W + (size_t)brow * N + bn + bcol;
    int tx = tid & 15, ty = tid >> 4;

    unsigned long long acc[8][4];
    #pragma unroll
    for (int i = 0; i < 8; i++)
        #pragma unroll
        for (int p = 0; p < 4; p++) acc[i][p] = 0ULL;

    float4 av = *(const float4*)Aptr;
    float4 bv = *(const float4*)Wptr;

    for (int k0 = 0; k0 < K; k0 += 8) {
        As[acol+0][arow] = av.x; As[acol+1][arow] = av.y;
        As[acol+2][arow] = av.z; As[acol+3][arow] = av.w;
        *(float4*)&Bs[brow][bcol] = bv;
        __syncthreads();
        if (k0 + 8 < K) {
            av = *(const float4*)(Aptr + k0 + 8);
            bv = *(const float4*)(Wptr + (size_t)(k0 + 8) * N);
        }
        #pragma unroll
        for (int k = 0; k < 8; k++) {
            float4 a0 = *(const float4*)&As[k][ty*8];
            float4 a1 = *(const float4*)&As[k][ty*8+4];
            ulonglong2 b01 = *(const ulonglong2*)&Bs[k][tx*8];
            ulonglong2 b23 = *(const ulonglong2*)&Bs[k][tx*8+4];
            unsigned long long bd[4] = {b01.x, b01.y, b23.x, b23.y};
            float a8[8] = {a0.x,a0.y,a0.z,a0.w,a1.x,a1.y,a1.z,a1.w};
            #pragma unroll
            for (int i = 0; i < 8; i++) {
                unsigned long long ad = pack2(a8[i], a8[i]);
                #pragma unroll
                for (int p = 0; p < 4; p++) fmaf2(acc[i][p], ad, bd[p]);
            }
        }
        __syncthreads();
    }

    float bb[8];
    #pragma unroll
    for (int j = 0; j < 8; j++) bb[j] = bias ? bias[bn + tx*8 + j] : 0.f;

    #pragma unroll
    for (int i = 0; i < 8; i++) {
        float f[8];
        #pragma unroll
        for (int p = 0; p < 4; p++) unpack2(acc[i][p], f[2*p], f[2*p+1]);
        size_t roff = (size_t)(bm + ty*8 + i) * N + bn + tx*8;
        #pragma unroll
        for (int jj = 0; jj < 8; jj += 4) {
            float v0 = (f[jj+0] + bb[jj+0]) * alpha;
            float v1 = (f[jj+1] + bb[jj+1]) * alpha;
            float v2 = (f[jj+2] + bb[jj+2]) * alpha;
            float v3 = (f[jj+3] + bb[jj+3]) * alpha;
            if (add) {
                float4 ad = *(const float4*)&add[roff + jj];
                v0 += ad.x; v1 += ad.y; v2 += ad.z; v3 += ad.w;
            }
            float4 o; o.x = v0; o.y = v1; o.z = v2; o.w = v3;
            *(float4*)&C[roff + jj] = o;
        }
    }
}

// ---------------------------------------------------------------------------
// Attention v2: two-pass register-tiled. Block = (b, h, 128-query stripe).
// Pass 1: stream kr tiles, online (max, sumexp) per row.
// Pass 2: recompute scores, write probs (gmem + smem pT), accumulate ctx.
// ---------------------------------------------------------------------------
#define AQT 128
#define QS  132
#define KS  132
#define VS  68
#define PS  136

__global__ __launch_bounds__(256, 1)
void attn2_kernel(const float* __restrict__ q, const float* __restrict__ kr,
                  const float* __restrict__ v, const int* __restrict__ mask,
                  float* __restrict__ probs, float* __restrict__ ctx)
{
    extern __shared__ float sm[];
    float* qT  = sm;                 // 64*132
    float* kT  = qT + 64*QS;         // 64*132
    float* vt  = kT + 64*KS;         // 128*68
    float* pT  = vt + 128*VS;        // 128*136 (also group-reduce buffer)
    float* Msm = pT + 128*PS;        // 128
    float* Lsm = Msm + 128;          // 128
    int*   msk = (int*)(Lsm + 128);  // 1024

    const int t0 = blockIdx.x * AQT;
    const int h  = blockIdx.y;
    const int b  = blockIdx.z;
    const int tid = threadIdx.x;
    const int ty = tid >> 4, tx = tid & 15;
    const int rr = tid >> 1, d0 = (tid & 1) * 32;

    const size_t baseQ  = ((size_t)(b*Tq + t0)) * Dq + h*DHq;
    const size_t baseKV = ((size_t)(b*Tq)) * Dq + h*DHq;

    // load q stripe transposed: qT[d][m]
    {
        const float* qp = q + baseQ + (size_t)rr * Dq + d0;
        #pragma unroll
        for (int i = 0; i < 8; i++) {
            float4 a = *(const float4*)(qp + i*4);
            qT[(d0+i*4+0)*QS + rr] = a.x;
            qT[(d0+i*4+1)*QS + rr] = a.y;
            qT[(d0+i*4+2)*QS + rr] = a.z;
            qT[(d0+i*4+3)*QS + rr] = a.w;
        }
    }
    for (int s = tid; s < Tq; s += 256) msk[s] = mask[b*Tq + s];

    // =================== PASS 1: row max + sumexp ===================
    float m8[8], l8[8];
    #pragma unroll
    for (int i = 0; i < 8; i++) { m8[i] = -1e30f; l8[i] = 0.f; }

    float4 kreg[8];
    {
        const float* kp = kr + baseKV + (size_t)rr * Dq + d0;
        #pragma unroll
        for (int i = 0; i < 8; i++) kreg[i] = *(const float4*)(kp + i*4);
    }

    for (int st = 0; st < 8; st++) {
        #pragma unroll
        for (int i = 0; i < 8; i++) {
            kT[(d0+i*4+0)*KS + rr] = kreg[i].x;
            kT[(d0+i*4+1)*KS + rr] = kreg[i].y;
            kT[(d0+i*4+2)*KS + rr] = kreg[i].z;
            kT[(d0+i*4+3)*KS + rr] = kreg[i].w;
        }
        __syncthreads();
        if (st < 7) {
            const float* kp = kr + baseKV + (size_t)((st+1)*128 + rr) * Dq + d0;
            #pragma unroll
            for (int i = 0; i < 8; i++) kreg[i] = *(const float4*)(kp + i*4);
        }

        unsigned long long sp[8][4];
        #pragma unroll
        for (int i = 0; i < 8; i++)
            #pragma unroll
            for (int p = 0; p < 4; p++) sp[i][p] = 0ULL;

        #pragma unroll 4
        for (int d = 0; d < 64; d++) {
            ulonglong2 kA = *(const ulonglong2*)&kT[d*KS + tx*8];
            ulonglong2 kB = *(const ulonglong2*)&kT[d*KS + tx*8 + 4];
            float4 qa = *(const float4*)&qT[d*QS + ty*8];
            float4 qb = *(const float4*)&qT[d*QS + ty*8 + 4];
            unsigned long long kd[4] = {kA.x, kA.y, kB.x, kB.y};
            float qv[8] = {qa.x,qa.y,qa.z,qa.w,qb.x,qb.y,qb.z,qb.w};
            #pragma unroll
            for (int i = 0; i < 8; i++) {
                unsigned long long qd = pack2(qv[i], qv[i]);
                #pragma unroll
                for (int p = 0; p < 4; p++) fmaf2(sp[i][p], qd, kd[p]);
            }
        }

        int s0 = st * 128;
        int mk[8];
        #pragma unroll
        for (int j = 0; j < 8; j++) mk[j] = msk[s0 + tx*8 + j];

        #pragma unroll
        for (int i = 0; i < 8; i++) {
            float sv[8];
            #pragma unroll
            for (int p = 0; p < 4; p++) unpack2(sp[i][p], sv[2*p], sv[2*p+1]);
            #pragma unroll
            for (int j = 0; j < 8; j++) sv[j] = mk[j] ? sv[j] : -1e9f;
            float mn = m8[i];
            #pragma unroll
            for (int j = 0; j < 8; j++) mn = fmaxf(mn, sv[j]);
            float sc = __expf(m8[i] - mn);
            float ss = 0.f;
            #pragma unroll
            for (int j = 0; j < 8; j++) ss += __expf(sv[j] - mn);
            l8[i] = l8[i]*sc + ss;
            m8[i] = mn;
        }
        __syncthreads();
    }

    // reduce stats across the 16 tx-threads of each q-block (same warp half)
    #pragma unroll
    for (int i = 0; i < 8; i++) {
        #pragma unroll
        for (int off = 8; off; off >>= 1) {
            float mo = __shfl_xor_sync(0xffffffffu, m8[i], off);
            float lo = __shfl_xor_sync(0xffffffffu, l8[i], off);
            float mn = fmaxf(m8[i], mo);
            l8[i] = l8[i]*__expf(m8[i]-mn) + lo*__expf(mo-mn);
            m8[i] = mn;
        }
    }
    if (tx == 0) {
        #pragma unroll
        for (int i = 0; i < 8; i++) {
            Msm[ty*8+i] = m8[i];
            Lsm[ty*8+i] = 1.0f / l8[i];
        }
    }
    __syncthreads();

    // =================== PASS 2: probs + ctx ===================
    float Mq[8], iL[8];
    #pragma unroll
    for (int i = 0; i < 8; i++) { Mq[i] = Msm[ty*8+i]; iL[i] = Lsm[ty*8+i]; }

    const int g  = tid >> 7;        // s-group for ctx GEMM
    const int r2 = tid & 127;
    const int qb = r2 >> 3, db = r2 & 7;
    unsigned long long oac[8][4];
    #pragma unroll
    for (int i = 0; i < 8; i++)
        #pragma unroll
        for (int p = 0; p < 4; p++) oac[i][p] = 0ULL;

    float4 vreg[8];
    {
        const float* kp = kr + baseKV + (size_t)rr * Dq + d0;
        const float* vp = v  + baseKV + (size_t)rr * Dq + d0;
        #pragma unroll
        for (int i = 0; i < 8; i++) {
            kreg[i] = *(const float4*)(kp + i*4);
            vreg[i] = *(const float4*)(vp + i*4);
        }
    }

    for (int st = 0; st < 8; st++) {
        #pragma unroll
        for (int i = 0; i < 8; i++) {
            kT[(d0+i*4+0)*KS + rr] = kreg[i].x;
            kT[(d0+i*4+1)*KS + rr] = kreg[i].y;
            kT[(d0+i*4+2)*KS + rr] = kreg[i].z;
            kT[(d0+i*4+3)*KS + rr] = kreg[i].w;
            *(float4*)&vt[rr*VS + d0 + i*4] = vreg[i];
        }
        __syncthreads();

        // recompute scores (identical to pass 1)
        unsigned long long sp[8][4];
        #pragma unroll
        for (int i = 0; i < 8; i++)
            #pragma unroll
            for (int p = 0; p < 4; p++) sp[i][p] = 0ULL;

        #pragma unroll 4
        for (int d = 0; d < 64; d++) {
            ulonglong2 kA = *(const ulonglong2*)&kT[d*KS + tx*8];
            ulonglong2 kB = *(const ulonglong2*)&kT[d*KS + tx*8 + 4];
            float4 qa = *(const float4*)&qT[d*QS + ty*8];
            float4 qb = *(const float4*)&qT[d*QS + ty*8 + 4];
            unsigned long long kd[4] = {kA.x, kA.y, kB.x, kB.y};
            float qv[8] = {qa.x,qa.y,qa.z,qa.w,qb.x,qb.y,qb.z,qb.w};
            #pragma unroll
            for (int i = 0; i < 8; i++) {
                unsigned long long qd = pack2(qv[i], qv[i]);
                #pragma unroll
                for (int p = 0; p < 4; p++) fmaf2(sp[i][p], qd, kd[p]);
            }
        }

        int s0 = st * 128;
        int mk[8];
        #pragma unroll
        for (int j = 0; j < 8; j++) mk[j] = msk[s0 + tx*8 + j];

        float pv[8][8];
        #pragma unroll
        for (int i = 0; i < 8; i++) {
            float sv[8];
            #pragma unroll
            for (int p = 0; p < 4; p++) unpack2(sp[i][p], sv[2*p], sv[2*p+1]);
            #pragma unroll
            for (int j = 0; j < 8; j++) {
                float val = mk[j] ? sv[j] : -1e9f;
                pv[i][j] = __expf(val - Mq[i]) * iL[i];
            }
        }
        // pT (transposed [s][q]) — j-order rotated by tx to spread banks
        #pragma unroll
        for (int jj = 0; jj < 8; jj++) {
            int j = (jj + tx) & 7;
            float4 w0 = make_float4(pv[0][j], pv[1][j], pv[2][j], pv[3][j]);
            float4 w1 = make_float4(pv[4][j], pv[5][j], pv[6][j], pv[7][j]);
            *(float4*)&pT[(tx*8+j)*PS + ty*8]     = w0;
            *(float4*)&pT[(tx*8+j)*PS + ty*8 + 4] = w1;
        }
        // probs gmem (coalesced)
        {
            size_t pbase = ((size_t)((b*Hq + h)*Tq + t0 + ty*8))*Tq + s0 + tx*8;
            #pragma unroll
            for (int i = 0; i < 8; i++) {
                float4 g0 = make_float4(pv[i][0], pv[i][1], pv[i][2], pv[i][3]);
                float4 g1 = make_float4(pv[i][4], pv[i][5], pv[i][6], pv[i][7]);
                *(float4*)&probs[pbase + (size_t)i*Tq]     = g0;
                *(float4*)&probs[pbase + (size_t)i*Tq + 4] = g1;
            }
        }
        // prefetch next tiles (overlaps with ctx compute)
        if (st < 7) {
            const float* kp = kr + baseKV + (size_t)((st+1)*128 + rr) * Dq + d0;
            const float* vp = v  + baseKV + (size_t)((st+1)*128 + rr) * Dq + d0;
            #pragma unroll
            for (int i = 0; i < 8; i++) {
                kreg[i] = *(const float4*)(kp + i*4);
                vreg[i] = *(const float4*)(vp + i*4);
            }
        }
        __syncthreads();

        // ctx accumulation: group g handles s in [g*64, g*64+64)
        #pragma unroll 4
        for (int ss = 0; ss < 64; ss++) {
            int s = g*64 + ss;
            float4 pa = *(const float4*)&pT[s*PS + qb*8];
            float4 pb = *(const float4*)&pT[s*PS + qb*8 + 4];
            ulonglong2 vA = *(const ulonglong2*)&vt[s*VS + db*8];
            ulonglong2 vB = *(const ulonglong2*)&vt[s*VS + db*8 + 4];
            unsigned long long vd[4] = {vA.x, vA.y, vB.x, vB.y};
            float pq[8] = {pa.x,pa.y,pa.z,pa.w,pb.x,pb.y,pb.z,pb.w};
            #pragma unroll
            for (int i = 0; i < 8; i++) {
                unsigned long long pd = pack2(pq[i], pq[i]);
                #pragma unroll
                for (int p = 0; p < 4; p++) fmaf2(oac[i][p], pd, vd[p]);
            }
        }
        __syncthreads();
    }

    // merge the two s-groups and store ctx
    if (g == 1) {
        #pragma unroll
        for (int i = 0; i < 8; i++) {
            float f[8];
            #pragma unroll
            for (int p = 0; p < 4; p++) unpack2(oac[i][p], f[2*p], f[2*p+1]);
            *(float4*)&pT[(qb*8+i)*64 + db*8]     = make_float4(f[0],f[1],f[2],f[3]);
            *(float4*)&pT[(qb*8+i)*64 + db*8 + 4] = make_float4(f[4],f[5],f[6],f[7]);
        }
    }
    __syncthreads();
    if (g == 0) {
        #pragma unroll
        for (int i = 0; i < 8; i++) {
            float f[8];
            #pragma unroll
            for (int p = 0; p < 4; p++) unpack2(oac[i][p], f[2*p], f[2*p+1]);
            float4 o0 = *(const float4*)&pT[(qb*8+i)*64 + db*8];
            float4 o1 = *(const float4*)&pT[(qb*8+i)*64 + db*8 + 4];
            f[0]+=o0.x; f[1]+=o0.y; f[2]+=o0.z; f[3]+=o0.w;
            f[4]+=o1.x; f[5]+=o1.y; f[6]+=o1.z; f[7]+=o1.w;
            size_t cbase = ((size_t)(b*Tq + t0 + qb*8 + i))*Dq + h*DHq + db*8;
            *(float4*)&ctx[cbase]     = make_float4(f[0],f[1],f[2],f[3]);
            *(float4*)&ctx[cbase + 4] = make_float4(f[4],f[5],f[6],f[7]);
        }
    }
}

// ---------------------------------------------------------------------------
extern "C" void kernel_launch(void* const* d_in, const int* in_sizes, int n_in,
                              void* d_out, int out_size)
{
    const float* query   = (const float*)d_in[0];
    const float* key     = (const float*)d_in[1];
    const float* value   = (const float*)d_in[2];
    const float* rel_pos = (const float*)d_in[3];
    const int*   kpm     = (const int*)  d_in[4];
    const float* qn_g = (const float*)d_in[5];
    const float* qn_b = (const float*)d_in[6];
    const float* kn_g = (const float*)d_in[7];
    const float* kn_b = (const float*)d_in[8];
    const float* vn_g = (const float*)d_in[9];
    const float* vn_b = (const float*)d_in[10];
    const float* Wq = (const float*)d_in[11];
    const float* bq = (const float*)d_in[12];
    const float* Wk = (const float*)d_in[13];
    const float* bk = (const float*)d_in[14];
    const float* Wv = (const float*)d_in[15];
    const float* bv = (const float*)d_in[16];
    const float* Wr = (const float*)d_in[17];
    const float* Wo = (const float*)d_in[18];
    const float* bo = (const float*)d_in[19];

    float* out   = (float*)d_out;
    float* probs = out + OUT_ELEMS;

    float *p_lnq, *p_lnk, *p_lnv, *p_q, *p_k, *p_v, *p_ctx;
    cudaGetSymbolAddress((void**)&p_lnq, g_lnq);
    cudaGetSymbolAddress((void**)&p_lnk, g_lnk);
    cudaGetSymbolAddress((void**)&p_lnv, g_lnv);
    cudaGetSymbolAddress((void**)&p_q,   g_q);
    cudaGetSymbolAddress((void**)&p_k,   g_k);
    cudaGetSymbolAddress((void**)&p_v,   g_v);
    cudaGetSymbolAddress((void**)&p_ctx, g_ctx);

    int smem_bytes = (64*QS + 64*KS + 128*VS + 128*PS + 256) * (int)sizeof(float)
                   + Tq * (int)sizeof(int);
    cudaFuncSetAttribute(attn2_kernel, cudaFuncAttributeMaxDynamicSharedMemorySize, smem_bytes);

    // 1) LayerNorms
    ln_kernel<<<Mrows, 256>>>(query, qn_g, qn_b, p_lnq);
    ln_kernel<<<Mrows, 256>>>(key,   kn_g, kn_b, p_lnk);
    ln_kernel<<<Mrows, 256>>>(value, vn_g, vn_b, p_lnv);

    dim3 ggrid(Dq/128, Mrows/128);
    // 2) q = (ln(query)@Wq + bq) * 0.125
    sgemm_kernel<<<ggrid, 256>>>(p_lnq, Wq, bq, nullptr, 0.125f, p_q, Mrows, Dq, Dq);
    // 3) k = ln(key)@Wk + bk
    sgemm_kernel<<<ggrid, 256>>>(p_lnk, Wk, bk, nullptr, 1.0f, p_k, Mrows, Dq, Dq);
    // 4) v = ln(value)@Wv + bv
    sgemm_kernel<<<ggrid, 256>>>(p_lnv, Wv, bv, nullptr, 1.0f, p_v, Mrows, Dq, Dq);
    // 5) kr = k + 0.1*(rel_pos@Wr)
    sgemm_kernel<<<ggrid, 256>>>(rel_pos, Wr, nullptr, p_k, 0.1f, p_k, Mrows, Dq, Dq);

    // 6) attention -> probs (gmem) + ctx
    dim3 agrid(Tq/AQT, Hq, Bq);
    attn2_kernel<<<agrid, 256, smem_bytes>>>(p_q, p_k, p_v, kpm, probs, p_ctx);

    // 7) out = ctx@Wo + bo
    sgemm_kernel<<<ggrid, 256>>>(p_ctx, Wo, bo, nullptr, 1.0f, out, Mrows, Dq, Dq);
}

// round 5
// speedup vs baseline: 1.7210x; 1.5000x over previous
#include <cuda_runtime.h>
#include <cuda_bf16.h>
#include <math.h>
#include <cstdint>

// Problem constants
#define Bq   4
#define Tq   1024
#define Dq   1024
#define Hq   16
#define DHq  64
#define Mrows (Bq*Tq)
#define OUT_ELEMS ((size_t)Mrows*Dq)

// ---------------- device scratch (no runtime allocation) -------------------
__device__ float g_q[Mrows*Dq];
__device__ float g_k[Mrows*Dq];   // becomes kr = k + 0.1*r in-place
__device__ float g_v[Mrows*Dq];
__device__ float g_ctx[Mrows*Dq];

// bf16 split operand buffers
__device__ __nv_bfloat16 g_lnq_h[Mrows*Dq], g_lnq_l[Mrows*Dq];
__device__ __nv_bfloat16 g_lnk_h[Mrows*Dq], g_lnk_l[Mrows*Dq];
__device__ __nv_bfloat16 g_lnv_h[Mrows*Dq], g_lnv_l[Mrows*Dq];
__device__ __nv_bfloat16 g_rp_h [Mrows*Dq], g_rp_l [Mrows*Dq];
__device__ __nv_bfloat16 g_ctx_h[Mrows*Dq], g_ctx_l[Mrows*Dq];
// transposed+split weights [N,K]
__device__ __nv_bfloat16 g_wq_h[Dq*Dq], g_wq_l[Dq*Dq];
__device__ __nv_bfloat16 g_wk_h[Dq*Dq], g_wk_l[Dq*Dq];
__device__ __nv_bfloat16 g_wv_h[Dq*Dq], g_wv_l[Dq*Dq];
__device__ __nv_bfloat16 g_wr_h[Dq*Dq], g_wr_l[Dq*Dq];
__device__ __nv_bfloat16 g_wo_h[Dq*Dq], g_wo_l[Dq*Dq];

// ------------------------- f32x2 packed helpers ----------------------------
__device__ __forceinline__ void fmaf2(unsigned long long &d,
                                      unsigned long long a,
                                      unsigned long long b) {
    asm("fma.rn.f32x2 %0, %1, %2, %0;" : "+l"(d) : "l"(a), "l"(b));
}
__device__ __forceinline__ unsigned long long pack2(float lo, float hi) {
    unsigned long long r;
    asm("mov.b64 %0, {%1, %2};" : "=l"(r) : "f"(lo), "f"(hi));
    return r;
}
__device__ __forceinline__ void unpack2(unsigned long long v, float &lo, float &hi) {
    asm("mov.b64 {%0, %1}, %2;" : "=f"(lo), "=f"(hi) : "l"(v));
}

// ------------------------- mma.sync / ldmatrix helpers ---------------------
__device__ __forceinline__ uint32_t smem_u32(const void* p) {
    uint32_t a;
    asm("{ .reg .u64 t; cvta.to.shared.u64 t, %1; cvt.u32.u64 %0, t; }"
        : "=r"(a) : "l"(p));
    return a;
}
#define LDSM_X4(r0, r1, r2, r3, addr)                                        \
    asm volatile("ldmatrix.sync.aligned.m8n8.x4.shared.b16 {%0,%1,%2,%3}, [%4];" \
        : "=r"(r0), "=r"(r1), "=r"(r2), "=r"(r3) : "r"(addr))

#define MMA16816(c, a, b)                                                    \
    asm volatile("mma.sync.aligned.m16n8k16.row.col.f32.bf16.bf16.f32 "      \
        "{%0,%1,%2,%3}, {%4,%5,%6,%7}, {%8,%9}, {%0,%1,%2,%3};"              \
        : "+f"((c)[0]), "+f"((c)[1]), "+f"((c)[2]), "+f"((c)[3])             \
        : "r"((a)[0]), "r"((a)[1]), "r"((a)[2]), "r"((a)[3]),                \
          "r"((b)[0]), "r"((b)[1]))

// ---------------------------------------------------------------------------
// LayerNorm over last dim (1024); outputs bf16 hi/lo split.
// ---------------------------------------------------------------------------
__global__ __launch_bounds__(256)
void ln_split_kernel(const float* __restrict__ x, const float* __restrict__ gamma,
                     const float* __restrict__ beta,
                     __nv_bfloat16* __restrict__ hi, __nv_bfloat16* __restrict__ lo)
{
    int row = blockIdx.x;
    int tid = threadIdx.x;
    const float4* xr = reinterpret_cast<const float4*>(x + (size_t)row * Dq);
    float4 v = xr[tid];
    float s  = v.x + v.y + v.z + v.w;
    float s2 = v.x*v.x + v.y*v.y + v.z*v.z + v.w*v.w;
    #pragma unroll
    for (int o = 16; o; o >>= 1) {
        s  += __shfl_xor_sync(0xffffffffu, s,  o);
        s2 += __shfl_xor_sync(0xffffffffu, s2, o);
    }
    __shared__ float ws[8], ws2[8], stats[2];
    int w = tid >> 5, lane = tid & 31;
    if (lane == 0) { ws[w] = s; ws2[w] = s2; }
    __syncthreads();
    if (tid == 0) {
        float ts = 0.f, ts2 = 0.f;
        #pragma unroll
        for (int i = 0; i < 8; i++) { ts += ws[i]; ts2 += ws2[i]; }
        float mu  = ts * (1.0f / Dq);
        float var = ts2 * (1.0f / Dq) - mu * mu;
        stats[0] = mu;
        stats[1] = rsqrtf(var + 1e-5f);
    }
    __syncthreads();
    float mu = stats[0], rstd = stats[1];
    float4 g = reinterpret_cast<const float4*>(gamma)[tid];
    float4 b = reinterpret_cast<const float4*>(beta)[tid];
    float o4[4];
    o4[0] = (v.x - mu) * rstd * g.x + b.x;
    o4[1] = (v.y - mu) * rstd * g.y + b.y;
    o4[2] = (v.z - mu) * rstd * g.z + b.z;
    o4[3] = (v.w - mu) * rstd * g.w + b.w;
    __nv_bfloat16 h4[4], l4[4];
    #pragma unroll
    for (int i = 0; i < 4; i++) {
        h4[i] = __float2bfloat16_rn(o4[i]);
        l4[i] = __float2bfloat16_rn(o4[i] - __bfloat162float(h4[i]));
    }
    *(ulonglong1*)&hi[(size_t)row * Dq + tid*4] = *(ulonglong1*)h4;
    *(ulonglong1*)&lo[(size_t)row * Dq + tid*4] = *(ulonglong1*)l4;
}

// plain fp32 -> bf16 hi/lo split (rel_pos, ctx)
__global__ __launch_bounds__(256)
void fsplit_kernel(const float* __restrict__ x,
                   __nv_bfloat16* __restrict__ hi, __nv_bfloat16* __restrict__ lo)
{
    size_t i = ((size_t)blockIdx.x * 256 + threadIdx.x) * 4;
    float4 v = *(const float4*)&x[i];
    float o4[4] = {v.x, v.y, v.z, v.w};
    __nv_bfloat16 h4[4], l4[4];
    #pragma unroll
    for (int j = 0; j < 4; j++) {
        h4[j] = __float2bfloat16_rn(o4[j]);
        l4[j] = __float2bfloat16_rn(o4[j] - __bfloat162float(h4[j]));
    }
    *(ulonglong1*)&hi[i] = *(ulonglong1*)h4;
    *(ulonglong1*)&lo[i] = *(ulonglong1*)l4;
}

// W [K,N] -> WT [N,K] bf16 hi/lo split (32x32 tiles)
__global__ __launch_bounds__(256)
void wsplit_kernel(const float* __restrict__ W,
                   __nv_bfloat16* __restrict__ hi, __nv_bfloat16* __restrict__ lo)
{
    __shared__ float t[32][33];
    int tx = threadIdx.x & 31, ty = threadIdx.x >> 5;   // 32 x 8
    int nb = blockIdx.x * 32, kb = blockIdx.y * 32;
    #pragma unroll
    for (int i = 0; i < 32; i += 8)
        t[ty+i][tx] = W[(size_t)(kb + ty + i) * Dq + nb + tx];
    __syncthreads();
    #pragma unroll
    for (int i = 0; i < 32; i += 8) {
        float v = t[tx][ty+i];
        __nv_bfloat16 h = __float2bfloat16_rn(v);
        size_t off = (size_t)(nb + ty + i) * Dq + kb + tx;
        hi[off] = h;
        lo[off] = __float2bfloat16_rn(v - __bfloat162float(h));
    }
}

// ---------------------------------------------------------------------------
// mma.sync GEMM, 3xBF16 emulated fp32:
//   C = alpha*(Ah@Bh^T + Ah@Bl^T + Al@Bh^T + bias) + add
// A*: [M,K] bf16 row-major.  B*: [N,K] bf16 row-major (pre-transposed W).
// CTA tile 128x128, K-chunk 64, 8 warps, warp tile 32x64.
// ---------------------------------------------------------------------------
#define GROW 72                         // padded bf16 per smem row (144B, 16B-mult)
#define GT   (128*GROW)                 // one operand tile in bf16 elems
#define GSM_BYTES (4*GT*2)              // 73728 B

__global__ __launch_bounds__(256, 1)
void mma_gemm_kernel(const __nv_bfloat16* __restrict__ Ah, const __nv_bfloat16* __restrict__ Al,
                     const __nv_bfloat16* __restrict__ Bh, const __nv_bfloat16* __restrict__ Bl,
                     const float* __restrict__ bias, const float* __restrict__ add,
                     float alpha, float* __restrict__ C, int M, int N, int K)
{
    extern __shared__ __nv_bfloat16 gsm[];
    __nv_bfloat16* sAh = gsm;
    __nv_bfloat16* sAl = gsm + GT;
    __nv_bfloat16* sBh = gsm + 2*GT;
    __nv_bfloat16* sBl = gsm + 3*GT;

    const int tid  = threadIdx.x;
    const int wid  = tid >> 5, lane = tid & 31;
    const int wm   = wid & 3,  wn   = wid >> 2;    // warp tile (wm*32, wn*64)
    const int bm = blockIdx.y * 128, bn = blockIdx.x * 128;

    // ldmatrix lane geometry
    const int g_row = (lane & 7) + ((lane >> 3) & 1) * 8;   // 0..15
    const int g_col = ((lane >> 4) & 1) * 8;                // 0 or 8

    const uint32_t uAh = smem_u32(sAh), uAl = smem_u32(sAl);
    const uint32_t uBh = smem_u32(sBh), uBl = smem_u32(sBl);

    // load geometry: c = tid + i*256; row = c>>3, col16 = c&7
    const int lrow0 = tid >> 3, lc16 = tid & 7;

    float acc[2][8][4];
    #pragma unroll
    for (int mt = 0; mt < 2; mt++)
        #pragma unroll
        for (int nf = 0; nf < 8; nf++)
            #pragma unroll
            for (int r = 0; r < 4; r++) acc[mt][nf][r] = 0.f;

    uint4 pf[16];
    #pragma unroll
    for (int i = 0; i < 4; i++) {
        int row = lrow0 + i * 32;
        pf[i]      = *(const uint4*)&Ah[(size_t)(bm + row) * K + lc16*8];
        pf[4 + i]  = *(const uint4*)&Al[(size_t)(bm + row) * K + lc16*8];
        pf[8 + i]  = *(const uint4*)&Bh[(size_t)(bn + row) * K + lc16*8];
        pf[12 + i] = *(const uint4*)&Bl[(size_t)(bn + row) * K + lc16*8];
    }

    const int nchunks = K / 64;
    for (int kc = 0; kc < nchunks; kc++) {
        #pragma unroll
        for (int i = 0; i < 4; i++) {
            int soff = (lrow0 + i*32) * GROW + lc16 * 8;
            *(uint4*)&sAh[soff] = pf[i];
            *(uint4*)&sAl[soff] = pf[4 + i];
            *(uint4*)&sBh[soff] = pf[8 + i];
            *(uint4*)&sBl[soff] = pf[12 + i];
        }
        __syncthreads();

        if (kc + 1 < nchunks) {
            int k0 = (kc + 1) * 64;
            #pragma unroll
            for (int i = 0; i < 4; i++) {
                int row = lrow0 + i * 32;
                pf[i]      = *(const uint4*)&Ah[(size_t)(bm + row) * K + k0 + lc16*8];
                pf[4 + i]  = *(const uint4*)&Al[(size_t)(bm + row) * K + k0 + lc16*8];
                pf[8 + i]  = *(const uint4*)&Bh[(size_t)(bn + row) * K + k0 + lc16*8];
                pf[12 + i] = *(const uint4*)&Bl[(size_t)(bn + row) * K + k0 + lc16*8];
            }
        }

        #pragma unroll
        for (int ks = 0; ks < 4; ks++) {
            const int kcol = ks * 16 + g_col;
            uint32_t ah[2][4], al[2][4];
            #pragma unroll
            for (int mt = 0; mt < 2; mt++) {
                uint32_t off = ((wm*32 + mt*16 + g_row) * GROW + kcol) * 2;
                LDSM_X4(ah[mt][0], ah[mt][1], ah[mt][2], ah[mt][3], uAh + off);
                LDSM_X4(al[mt][0], al[mt][1], al[mt][2], al[mt][3], uAl + off);
            }
            uint32_t bh[8][2], bl[8][2];
            #pragma unroll
            for (int np = 0; np < 4; np++) {
                uint32_t off = ((wn*64 + np*16 + g_row) * GROW + kcol) * 2;
                uint32_t r0, r1, r2, r3;
                LDSM_X4(r0, r1, r2, r3, uBh + off);
                bh[2*np][0] = r0;   bh[2*np][1] = r2;
                bh[2*np+1][0] = r1; bh[2*np+1][1] = r3;
                LDSM_X4(r0, r1, r2, r3, uBl + off);
                bl[2*np][0] = r0;   bl[2*np][1] = r2;
                bl[2*np+1][0] = r1; bl[2*np+1][1] = r3;
            }
            #pragma unroll
            for (int mt = 0; mt < 2; mt++)
                #pragma unroll
                for (int nf = 0; nf < 8; nf++) {
                    MMA16816(acc[mt][nf], ah[mt], bh[nf]);
                    MMA16816(acc[mt][nf], ah[mt], bl[nf]);
                    MMA16816(acc[mt][nf], al[mt], bh[nf]);
                }
        }
        __syncthreads();
    }

    // epilogue: thread holds (rows r0,r0+8) x (2 cols) per frag
    const int qrow = lane >> 2, qcol = (lane & 3) * 2;
    #pragma unroll
    for (int mt = 0; mt < 2; mt++) {
        int r0 = bm + wm*32 + mt*16 + qrow;
        #pragma unroll
        for (int nf = 0; nf < 8; nf++) {
            int col = bn + wn*64 + nf*8 + qcol;
            float2 vb = bias ? *(const float2*)&bias[col] : make_float2(0.f, 0.f);
            float2 o0, o1;
            o0.x = alpha * (acc[mt][nf][0] + vb.x);
            o0.y = alpha * (acc[mt][nf][1] + vb.y);
            o1.x = alpha * (acc[mt][nf][2] + vb.x);
            o1.y = alpha * (acc[mt][nf][3] + vb.y);
            size_t off0 = (size_t)r0 * N + col;
            size_t off1 = (size_t)(r0 + 8) * N + col;
            if (add) {
                float2 a0 = *(const float2*)&add[off0];
                float2 a1 = *(const float2*)&add[off1];
                o0.x += a0.x; o0.y += a0.y;
                o1.x += a1.x; o1.y += a1.y;
            }
            *(float2*)&C[off0] = o0;
            *(float2*)&C[off1] = o1;
        }
    }
}

// ---------------------------------------------------------------------------
// Attention v2 (unchanged): two-pass register-tiled with f32x2 FMA.
// ---------------------------------------------------------------------------
#define AQT 128
#define QS  132
#define KS  132
#define VS  68
#define PS  136

__global__ __launch_bounds__(256, 1)
void attn2_kernel(const float* __restrict__ q, const float* __restrict__ kr,
                  const float* __restrict__ v, const int* __restrict__ mask,
                  float* __restrict__ probs, float* __restrict__ ctx)
{
    extern __shared__ float sm[];
    float* qT  = sm;                 // 64*132
    float* kT  = qT + 64*QS;         // 64*132
    float* vt  = kT + 64*KS;         // 128*68
    float* pT  = vt + 128*VS;        // 128*136
    float* Msm = pT + 128*PS;        // 128
    float* Lsm = Msm + 128;          // 128
    int*   msk = (int*)(Lsm + 128);  // 1024

    const int t0 = blockIdx.x * AQT;
    const int h  = blockIdx.y;
    const int b  = blockIdx.z;
    const int tid = threadIdx.x;
    const int ty = tid >> 4, tx = tid & 15;
    const int rr = tid >> 1, d0 = (tid & 1) * 32;

    const size_t baseQ  = ((size_t)(b*Tq + t0)) * Dq + h*DHq;
    const size_t baseKV = ((size_t)(b*Tq)) * Dq + h*DHq;

    {
        const float* qp = q + baseQ + (size_t)rr * Dq + d0;
        #pragma unroll
        for (int i = 0; i < 8; i++) {
            float4 a = *(const float4*)(qp + i*4);
            qT[(d0+i*4+0)*QS + rr] = a.x;
            qT[(d0+i*4+1)*QS + rr] = a.y;
            qT[(d0+i*4+2)*QS + rr] = a.z;
            qT[(d0+i*4+3)*QS + rr] = a.w;
        }
    }
    for (int s = tid; s < Tq; s += 256) msk[s] = mask[b*Tq + s];

    // =================== PASS 1: row max + sumexp ===================
    float m8[8], l8[8];
    #pragma unroll
    for (int i = 0; i < 8; i++) { m8[i] = -1e30f; l8[i] = 0.f; }

    float4 kreg[8];
    {
        const float* kp = kr + baseKV + (size_t)rr * Dq + d0;
        #pragma unroll
        for (int i = 0; i < 8; i++) kreg[i] = *(const float4*)(kp + i*4);
    }

    for (int st = 0; st < 8; st++) {
        #pragma unroll
        for (int i = 0; i < 8; i++) {
            kT[(d0+i*4+0)*KS + rr] = kreg[i].x;
            kT[(d0+i*4+1)*KS + rr] = kreg[i].y;
            kT[(d0+i*4+2)*KS + rr] = kreg[i].z;
            kT[(d0+i*4+3)*KS + rr] = kreg[i].w;
        }
        __syncthreads();
        if (st < 7) {
            const float* kp = kr + baseKV + (size_t)((st+1)*128 + rr) * Dq + d0;
            #pragma unroll
            for (int i = 0; i < 8; i++) kreg[i] = *(const float4*)(kp + i*4);
        }

        unsigned long long sp[8][4];
        #pragma unroll
        for (int i = 0; i < 8; i++)
            #pragma unroll
            for (int p = 0; p < 4; p++) sp[i][p] = 0ULL;

        #pragma unroll 4
        for (int d = 0; d < 64; d++) {
            ulonglong2 kA = *(const ulonglong2*)&kT[d*KS + tx*8];
            ulonglong2 kB = *(const ulonglong2*)&kT[d*KS + tx*8 + 4];
            float4 qa = *(const float4*)&qT[d*QS + ty*8];
            float4 qb = *(const float4*)&qT[d*QS + ty*8 + 4];
            unsigned long long kd[4] = {kA.x, kA.y, kB.x, kB.y};
            float qv[8] = {qa.x,qa.y,qa.z,qa.w,qb.x,qb.y,qb.z,qb.w};
            #pragma unroll
            for (int i = 0; i < 8; i++) {
                unsigned long long qd = pack2(qv[i], qv[i]);
                #pragma unroll
                for (int p = 0; p < 4; p++) fmaf2(sp[i][p], qd, kd[p]);
            }
        }

        int s0 = st * 128;
        int mk[8];
        #pragma unroll
        for (int j = 0; j < 8; j++) mk[j] = msk[s0 + tx*8 + j];

        #pragma unroll
        for (int i = 0; i < 8; i++) {
            float sv[8];
            #pragma unroll
            for (int p = 0; p < 4; p++) unpack2(sp[i][p], sv[2*p], sv[2*p+1]);
            #pragma unroll
            for (int j = 0; j < 8; j++) sv[j] = mk[j] ? sv[j] : -1e9f;
            float mn = m8[i];
            #pragma unroll
            for (int j = 0; j < 8; j++) mn = fmaxf(mn, sv[j]);
            float sc = __expf(m8[i] - mn);
            float ss = 0.f;
            #pragma unroll
            for (int j = 0; j < 8; j++) ss += __expf(sv[j] - mn);
            l8[i] = l8[i]*sc + ss;
            m8[i] = mn;
        }
        __syncthreads();
    }

    #pragma unroll
    for (int i = 0; i < 8; i++) {
        #pragma unroll
        for (int off = 8; off; off >>= 1) {
            float mo = __shfl_xor_sync(0xffffffffu, m8[i], off);
            float lo = __shfl_xor_sync(0xffffffffu, l8[i], off);
            float mn = fmaxf(m8[i], mo);
            l8[i] = l8[i]*__expf(m8[i]-mn) + lo*__expf(mo-mn);
            m8[i] = mn;
        }
    }
    if (tx == 0) {
        #pragma unroll
        for (int i = 0; i < 8; i++) {
            Msm[ty*8+i] = m8[i];
            Lsm[ty*8+i] = 1.0f / l8[i];
        }
    }
    __syncthreads();

    // =================== PASS 2: probs + ctx ===================
    float Mq[8], iL[8];
    #pragma unroll
    for (int i = 0; i < 8; i++) { Mq[i] = Msm[ty*8+i]; iL[i] = Lsm[ty*8+i]; }

    const int g  = tid >> 7;
    const int r2 = tid & 127;
    const int qb = r2 >> 3, db = r2 & 7;
    unsigned long long oac[8][4];
    #pragma unroll
    for (int i = 0; i < 8; i++)
        #pragma unroll
        for (int p = 0; p < 4; p++) oac[i][p] = 0ULL;

    float4 vreg[8];
    {
        const float* kp = kr + baseKV + (size_t)rr * Dq + d0;
        const float* vp = v  + baseKV + (size_t)rr * Dq + d0;
        #pragma unroll
        for (int i = 0; i < 8; i++) {
            kreg[i] = *(const float4*)(kp + i*4);
            vreg[i] = *(const float4*)(vp + i*4);
        }
    }

    for (int st = 0; st < 8; st++) {
        #pragma unroll
        for (int i = 0; i < 8; i++) {
            kT[(d0+i*4+0)*KS + rr] = kreg[i].x;
            kT[(d0+i*4+1)*KS + rr] = kreg[i].y;
            kT[(d0+i*4+2)*KS + rr] = kreg[i].z;
            kT[(d0+i*4+3)*KS + rr] = kreg[i].w;
            *(float4*)&vt[rr*VS + d0 + i*4] = vreg[i];
        }
        __syncthreads();

        unsigned long long sp[8][4];
        #pragma unroll
        for (int i = 0; i < 8; i++)
            #pragma unroll
            for (int p = 0; p < 4; p++) sp[i][p] = 0ULL;

        #pragma unroll 4
        for (int d = 0; d < 64; d++) {
            ulonglong2 kA = *(const ulonglong2*)&kT[d*KS + tx*8];
            ulonglong2 kB = *(const ulonglong2*)&kT[d*KS + tx*8 + 4];
            float4 qa = *(const float4*)&qT[d*QS + ty*8];
            float4 qb = *(const float4*)&qT[d*QS + ty*8 + 4];
            unsigned long long kd[4] = {kA.x, kA.y, kB.x, kB.y};
            float qv[8] = {qa.x,qa.y,qa.z,qa.w,qb.x,qb.y,qb.z,qb.w};
            #pragma unroll
            for (int i = 0; i < 8; i++) {
                unsigned long long qd = pack2(qv[i], qv[i]);
                #pragma unroll
                for (int p = 0; p < 4; p++) fmaf2(sp[i][p], qd, kd[p]);
            }
        }

        int s0 = st * 128;
        int mk[8];
        #pragma unroll
        for (int j = 0; j < 8; j++) mk[j] = msk[s0 + tx*8 + j];

        float pv[8][8];
        #pragma unroll
        for (int i = 0; i < 8; i++) {
            float sv[8];
            #pragma unroll
            for (int p = 0; p < 4; p++) unpack2(sp[i][p], sv[2*p], sv[2*p+1]);
            #pragma unroll
            for (int j = 0; j < 8; j++) {
                float val = mk[j] ? sv[j] : -1e9f;
                pv[i][j] = __expf(val - Mq[i]) * iL[i];
            }
        }
        #pragma unroll
        for (int jj = 0; jj < 8; jj++) {
            int j = (jj + tx) & 7;
            float4 w0 = make_float4(pv[0][j], pv[1][j], pv[2][j], pv[3][j]);
            float4 w1 = make_float4(pv[4][j], pv[5][j], pv[6][j], pv[7][j]);
            *(float4*)&pT[(tx*8+j)*PS + ty*8]     = w0;
            *(float4*)&pT[(tx*8+j)*PS + ty*8 + 4] = w1;
        }
        {
            size_t pbase = ((size_t)((b*Hq + h)*Tq + t0 + ty*8))*Tq + s0 + tx*8;
            #pragma unroll
            for (int i = 0; i < 8; i++) {
                float4 g0 = make_float4(pv[i][0], pv[i][1], pv[i][2], pv[i][3]);
                float4 g1 = make_float4(pv[i][4], pv[i][5], pv[i][6], pv[i][7]);
                *(float4*)&probs[pbase + (size_t)i*Tq]     = g0;
                *(float4*)&probs[pbase + (size_t)i*Tq + 4] = g1;
            }
        }
        if (st < 7) {
            const float* kp = kr + baseKV + (size_t)((st+1)*128 + rr) * Dq + d0;
            const float* vp = v  + baseKV + (size_t)((st+1)*128 + rr) * Dq + d0;
            #pragma unroll
            for (int i = 0; i < 8; i++) {
                kreg[i] = *(const float4*)(kp + i*4);
                vreg[i] = *(const float4*)(vp + i*4);
            }
        }
        __syncthreads();

        #pragma unroll 4
        for (int ss = 0; ss < 64; ss++) {
            int s = g*64 + ss;
            float4 pa = *(const float4*)&pT[s*PS + qb*8];
            float4 pb = *(const float4*)&pT[s*PS + qb*8 + 4];
            ulonglong2 vA = *(const ulonglong2*)&vt[s*VS + db*8];
            ulonglong2 vB = *(const ulonglong2*)&vt[s*VS + db*8 + 4];
            unsigned long long vd[4] = {vA.x, vA.y, vB.x, vB.y};
            float pq[8] = {pa.x,pa.y,pa.z,pa.w,pb.x,pb.y,pb.z,pb.w};
            #pragma unroll
            for (int i = 0; i < 8; i++) {
                unsigned long long pd = pack2(pq[i], pq[i]);
                #pragma unroll
                for (int p = 0; p < 4; p++) fmaf2(oac[i][p], pd, vd[p]);
            }
        }
        __syncthreads();
    }

    if (g == 1) {
        #pragma unroll
        for (int i = 0; i < 8; i++) {
            float f[8];
            #pragma unroll
            for (int p = 0; p < 4; p++) unpack2(oac[i][p], f[2*p], f[2*p+1]);
            *(float4*)&pT[(qb*8+i)*64 + db*8]     = make_float4(f[0],f[1],f[2],f[3]);
            *(float4*)&pT[(qb*8+i)*64 + db*8 + 4] = make_float4(f[4],f[5],f[6],f[7]);
        }
    }
    __syncthreads();
    if (g == 0) {
        #pragma unroll
        for (int i = 0; i < 8; i++) {
            float f[8];
            #pragma unroll
            for (int p = 0; p < 4; p++) unpack2(oac[i][p], f[2*p], f[2*p+1]);
            float4 o0 = *(const float4*)&pT[(qb*8+i)*64 + db*8];
            float4 o1 = *(const float4*)&pT[(qb*8+i)*64 + db*8 + 4];
            f[0]+=o0.x; f[1]+=o0.y; f[2]+=o0.z; f[3]+=o0.w;
            f[4]+=o1.x; f[5]+=o1.y; f[6]+=o1.z; f[7]+=o1.w;
            size_t cbase = ((size_t)(b*Tq + t0 + qb*8 + i))*Dq + h*DHq + db*8;
            *(float4*)&ctx[cbase]     = make_float4(f[0],f[1],f[2],f[3]);
            *(float4*)&ctx[cbase + 4] = make_float4(f[4],f[5],f[6],f[7]);
        }
    }
}

// ---------------------------------------------------------------------------
extern "C" void kernel_launch(void* const* d_in, const int* in_sizes, int n_in,
                              void* d_out, int out_size)
{
    const float* query   = (const float*)d_in[0];
    const float* key     = (const float*)d_in[1];
    const float* value   = (const float*)d_in[2];
    const float* rel_pos = (const float*)d_in[3];
    const int*   kpm     = (const int*)  d_in[4];
    const float* qn_g = (const float*)d_in[5];
    const float* qn_b = (const float*)d_in[6];
    const float* kn_g = (const float*)d_in[7];
    const float* kn_b = (const float*)d_in[8];
    const float* vn_g = (const float*)d_in[9];
    const float* vn_b = (const float*)d_in[10];
    const float* Wq = (const float*)d_in[11];
    const float* bq = (const float*)d_in[12];
    const float* Wk = (const float*)d_in[13];
    const float* bk = (const float*)d_in[14];
    const float* Wv = (const float*)d_in[15];
    const float* bv = (const float*)d_in[16];
    const float* Wr = (const float*)d_in[17];
    const float* Wo = (const float*)d_in[18];
    const float* bo = (const float*)d_in[19];

    float* out   = (float*)d_out;
    float* probs = out + OUT_ELEMS;

    float *p_q, *p_k, *p_v, *p_ctx;
    cudaGetSymbolAddress((void**)&p_q,   g_q);
    cudaGetSymbolAddress((void**)&p_k,   g_k);
    cudaGetSymbolAddress((void**)&p_v,   g_v);
    cudaGetSymbolAddress((void**)&p_ctx, g_ctx);

    __nv_bfloat16 *lnq_h,*lnq_l,*lnk_h,*lnk_l,*lnv_h,*lnv_l,*rp_h,*rp_l,*ctx_h,*ctx_l;
    __nv_bfloat16 *wq_h,*wq_l,*wk_h,*wk_l,*wv_h,*wv_l,*wr_h,*wr_l,*wo_h,*wo_l;
    cudaGetSymbolAddress((void**)&lnq_h, g_lnq_h); cudaGetSymbolAddress((void**)&lnq_l, g_lnq_l);
    cudaGetSymbolAddress((void**)&lnk_h, g_lnk_h); cudaGetSymbolAddress((void**)&lnk_l, g_lnk_l);
    cudaGetSymbolAddress((void**)&lnv_h, g_lnv_h); cudaGetSymbolAddress((void**)&lnv_l, g_lnv_l);
    cudaGetSymbolAddress((void**)&rp_h,  g_rp_h);  cudaGetSymbolAddress((void**)&rp_l,  g_rp_l);
    cudaGetSymbolAddress((void**)&ctx_h, g_ctx_h); cudaGetSymbolAddress((void**)&ctx_l, g_ctx_l);
    cudaGetSymbolAddress((void**)&wq_h, g_wq_h);   cudaGetSymbolAddress((void**)&wq_l, g_wq_l);
    cudaGetSymbolAddress((void**)&wk_h, g_wk_h);   cudaGetSymbolAddress((void**)&wk_l, g_wk_l);
    cudaGetSymbolAddress((void**)&wv_h, g_wv_h);   cudaGetSymbolAddress((void**)&wv_l, g_wv_l);
    cudaGetSymbolAddress((void**)&wr_h, g_wr_h);   cudaGetSymbolAddress((void**)&wr_l, g_wr_l);
    cudaGetSymbolAddress((void**)&wo_h, g_wo_h);   cudaGetSymbolAddress((void**)&wo_l, g_wo_l);

    int attn_smem = (64*QS + 64*KS + 128*VS + 128*PS + 256) * (int)sizeof(float)
                  + Tq * (int)sizeof(int);
    cudaFuncSetAttribute(attn2_kernel, cudaFuncAttributeMaxDynamicSharedMemorySize, attn_smem);
    cudaFuncSetAttribute(mma_gemm_kernel, cudaFuncAttributeMaxDynamicSharedMemorySize, GSM_BYTES);

    // 1) weight transpose + split (5x)
    dim3 wgrid(Dq/32, Dq/32);
    wsplit_kernel<<<wgrid, 256>>>(Wq, wq_h, wq_l);
    wsplit_kernel<<<wgrid, 256>>>(Wk, wk_h, wk_l);
    wsplit_kernel<<<wgrid, 256>>>(Wv, wv_h, wv_l);
    wsplit_kernel<<<wgrid, 256>>>(Wr, wr_h, wr_l);
    wsplit_kernel<<<wgrid, 256>>>(Wo, wo_h, wo_l);

    // 2) LayerNorms with bf16 split output + rel_pos split
    ln_split_kernel<<<Mrows, 256>>>(query, qn_g, qn_b, lnq_h, lnq_l);
    ln_split_kernel<<<Mrows, 256>>>(key,   kn_g, kn_b, lnk_h, lnk_l);
    ln_split_kernel<<<Mrows, 256>>>(value, vn_g, vn_b, lnv_h, lnv_l);
    fsplit_kernel<<<(Mrows*Dq)/1024, 256>>>(rel_pos, rp_h, rp_l);

    // 3) projection GEMMs on tensor cores (mma.sync)
    dim3 ggrid(Dq/128, Mrows/128);
    mma_gemm_kernel<<<ggrid, 256, GSM_BYTES>>>(lnq_h, lnq_l, wq_h, wq_l, bq, nullptr, 0.125f, p_q, Mrows, Dq, Dq);
    mma_gemm_kernel<<<ggrid, 256, GSM_BYTES>>>(lnk_h, lnk_l, wk_h, wk_l, bk, nullptr, 1.0f,   p_k, Mrows, Dq, Dq);
    mma_gemm_kernel<<<ggrid, 256, GSM_BYTES>>>(lnv_h, lnv_l, wv_h, wv_l, bv, nullptr, 1.0f,   p_v, Mrows, Dq, Dq);
    mma_gemm_kernel<<<ggrid, 256, GSM_BYTES>>>(rp_h,  rp_l,  wr_h, wr_l, nullptr, p_k, 0.1f,  p_k, Mrows, Dq, Dq);

    // 4) attention -> probs (gmem) + ctx
    dim3 agrid(Tq/AQT, Hq, Bq);
    attn2_kernel<<<agrid, 256, attn_smem>>>(p_q, p_k, p_v, kpm, probs, p_ctx);

    // 5) out = ctx@Wo + bo
    fsplit_kernel<<<(Mrows*Dq)/1024, 256>>>(p_ctx, ctx_h, ctx_l);
    mma_gemm_kernel<<<ggrid, 256, GSM_BYTES>>>(ctx_h, ctx_l, wo_h, wo_l, bo, nullptr, 1.0f, out, Mrows, Dq, Dq);
}

// round 6
// speedup vs baseline: 2.5057x; 1.4559x over previous
#include <cuda_runtime.h>
#include <cuda_bf16.h>
#include <math.h>
#include <cstdint>

// Problem constants
#define Bq   4
#define Tq   1024
#define Dq   1024
#define Hq   16
#define DHq  64
#define Mrows (Bq*Tq)
#define OUT_ELEMS ((size_t)Mrows*Dq)

// ---------------- device scratch (no runtime allocation) -------------------
__device__ float g_q[Mrows*Dq];
__device__ float g_k[Mrows*Dq];   // becomes kr = k + 0.1*r in-place
__device__ float g_v[Mrows*Dq];

// bf16 split operand buffers
__device__ __nv_bfloat16 g_lnq_h[Mrows*Dq], g_lnq_l[Mrows*Dq];
__device__ __nv_bfloat16 g_lnk_h[Mrows*Dq], g_lnk_l[Mrows*Dq];
__device__ __nv_bfloat16 g_lnv_h[Mrows*Dq], g_lnv_l[Mrows*Dq];
__device__ __nv_bfloat16 g_rp_h [Mrows*Dq], g_rp_l [Mrows*Dq];
__device__ __nv_bfloat16 g_ctx_h[Mrows*Dq], g_ctx_l[Mrows*Dq];
// transposed+split weights [N,K]
__device__ __nv_bfloat16 g_wq_h[Dq*Dq], g_wq_l[Dq*Dq];
__device__ __nv_bfloat16 g_wk_h[Dq*Dq], g_wk_l[Dq*Dq];
__device__ __nv_bfloat16 g_wv_h[Dq*Dq], g_wv_l[Dq*Dq];
__device__ __nv_bfloat16 g_wr_h[Dq*Dq], g_wr_l[Dq*Dq];
__device__ __nv_bfloat16 g_wo_h[Dq*Dq], g_wo_l[Dq*Dq];

// ------------------------- mma.sync / ldmatrix helpers ---------------------
__device__ __forceinline__ uint32_t smem_u32(const void* p) {
    uint32_t a;
    asm("{ .reg .u64 t; cvta.to.shared.u64 t, %1; cvt.u32.u64 %0, t; }"
        : "=r"(a) : "l"(p));
    return a;
}
#define LDSM_X4(r0, r1, r2, r3, addr)                                        \
    asm volatile("ldmatrix.sync.aligned.m8n8.x4.shared.b16 {%0,%1,%2,%3}, [%4];" \
        : "=r"(r0), "=r"(r1), "=r"(r2), "=r"(r3) : "r"(addr))

#define LDSM_T_X4(r0, r1, r2, r3, addr)                                      \
    asm volatile("ldmatrix.sync.aligned.m8n8.x4.trans.shared.b16 {%0,%1,%2,%3}, [%4];" \
        : "=r"(r0), "=r"(r1), "=r"(r2), "=r"(r3) : "r"(addr))

#define MMA16816(c, a, b)                                                    \
    asm volatile("mma.sync.aligned.m16n8k16.row.col.f32.bf16.bf16.f32 "      \
        "{%0,%1,%2,%3}, {%4,%5,%6,%7}, {%8,%9}, {%0,%1,%2,%3};"              \
        : "+f"((c)[0]), "+f"((c)[1]), "+f"((c)[2]), "+f"((c)[3])             \
        : "r"((a)[0]), "r"((a)[1]), "r"((a)[2]), "r"((a)[3]),                \
          "r"((b)[0]), "r"((b)[1]))

// pack two fp32 -> bf16x2 reg (lo in low half)
__device__ __forceinline__ uint32_t bf2x(float lo, float hi) {
    uint32_t r;
    asm("cvt.rn.bf16x2.f32 %0, %1, %2;" : "=r"(r) : "f"(hi), "f"(lo));
    return r;
}

// ---------------------------------------------------------------------------
// LayerNorm over last dim (1024); outputs bf16 hi/lo split.
// ---------------------------------------------------------------------------
__global__ __launch_bounds__(256)
void ln_split_kernel(const float* __restrict__ x, const float* __restrict__ gamma,
                     const float* __restrict__ beta,
                     __nv_bfloat16* __restrict__ hi, __nv_bfloat16* __restrict__ lo)
{
    int row = blockIdx.x;
    int tid = threadIdx.x;
    const float4* xr = reinterpret_cast<const float4*>(x + (size_t)row * Dq);
    float4 v = xr[tid];
    float s  = v.x + v.y + v.z + v.w;
    float s2 = v.x*v.x + v.y*v.y + v.z*v.z + v.w*v.w;
    #pragma unroll
    for (int o = 16; o; o >>= 1) {
        s  += __shfl_xor_sync(0xffffffffu, s,  o);
        s2 += __shfl_xor_sync(0xffffffffu, s2, o);
    }
    __shared__ float ws[8], ws2[8], stats[2];
    int w = tid >> 5, lane = tid & 31;
    if (lane == 0) { ws[w] = s; ws2[w] = s2; }
    __syncthreads();
    if (tid == 0) {
        float ts = 0.f, ts2 = 0.f;
        #pragma unroll
        for (int i = 0; i < 8; i++) { ts += ws[i]; ts2 += ws2[i]; }
        float mu  = ts * (1.0f / Dq);
        float var = ts2 * (1.0f / Dq) - mu * mu;
        stats[0] = mu;
        stats[1] = rsqrtf(var + 1e-5f);
    }
    __syncthreads();
    float mu = stats[0], rstd = stats[1];
    float4 g = reinterpret_cast<const float4*>(gamma)[tid];
    float4 b = reinterpret_cast<const float4*>(beta)[tid];
    float o4[4];
    o4[0] = (v.x - mu) * rstd * g.x + b.x;
    o4[1] = (v.y - mu) * rstd * g.y + b.y;
    o4[2] = (v.z - mu) * rstd * g.z + b.z;
    o4[3] = (v.w - mu) * rstd * g.w + b.w;
    __nv_bfloat16 h4[4], l4[4];
    #pragma unroll
    for (int i = 0; i < 4; i++) {
        h4[i] = __float2bfloat16_rn(o4[i]);
        l4[i] = __float2bfloat16_rn(o4[i] - __bfloat162float(h4[i]));
    }
    *(ulonglong1*)&hi[(size_t)row * Dq + tid*4] = *(ulonglong1*)h4;
    *(ulonglong1*)&lo[(size_t)row * Dq + tid*4] = *(ulonglong1*)l4;
}

// plain fp32 -> bf16 hi/lo split (rel_pos)
__global__ __launch_bounds__(256)
void fsplit_kernel(const float* __restrict__ x,
                   __nv_bfloat16* __restrict__ hi, __nv_bfloat16* __restrict__ lo)
{
    size_t i = ((size_t)blockIdx.x * 256 + threadIdx.x) * 4;
    float4 v = *(const float4*)&x[i];
    float o4[4] = {v.x, v.y, v.z, v.w};
    __nv_bfloat16 h4[4], l4[4];
    #pragma unroll
    for (int j = 0; j < 4; j++) {
        h4[j] = __float2bfloat16_rn(o4[j]);
        l4[j] = __float2bfloat16_rn(o4[j] - __bfloat162float(h4[j]));
    }
    *(ulonglong1*)&hi[i] = *(ulonglong1*)h4;
    *(ulonglong1*)&lo[i] = *(ulonglong1*)l4;
}

// W [K,N] -> WT [N,K] bf16 hi/lo split (32x32 tiles)
__global__ __launch_bounds__(256)
void wsplit_kernel(const float* __restrict__ W,
                   __nv_bfloat16* __restrict__ hi, __nv_bfloat16* __restrict__ lo)
{
    __shared__ float t[32][33];
    int tx = threadIdx.x & 31, ty = threadIdx.x >> 5;   // 32 x 8
    int nb = blockIdx.x * 32, kb = blockIdx.y * 32;
    #pragma unroll
    for (int i = 0; i < 32; i += 8)
        t[ty+i][tx] = W[(size_t)(kb + ty + i) * Dq + nb + tx];
    __syncthreads();
    #pragma unroll
    for (int i = 0; i < 32; i += 8) {
        float v = t[tx][ty+i];
        __nv_bfloat16 h = __float2bfloat16_rn(v);
        size_t off = (size_t)(nb + ty + i) * Dq + kb + tx;
        hi[off] = h;
        lo[off] = __float2bfloat16_rn(v - __bfloat162float(h));
    }
}

// ---------------------------------------------------------------------------
// mma.sync GEMM, 3xBF16 emulated fp32 (unchanged from round 4/5 — validated)
// ---------------------------------------------------------------------------
#define GROW 72
#define GT   (128*GROW)
#define GSM_BYTES (4*GT*2)

__global__ __launch_bounds__(256, 1)
void mma_gemm_kernel(const __nv_bfloat16* __restrict__ Ah, const __nv_bfloat16* __restrict__ Al,
                     const __nv_bfloat16* __restrict__ Bh, const __nv_bfloat16* __restrict__ Bl,
                     const float* __restrict__ bias, const float* __restrict__ add,
                     float alpha, float* __restrict__ C, int M, int N, int K)
{
    extern __shared__ __nv_bfloat16 gsm[];
    __nv_bfloat16* sAh = gsm;
    __nv_bfloat16* sAl = gsm + GT;
    __nv_bfloat16* sBh = gsm + 2*GT;
    __nv_bfloat16* sBl = gsm + 3*GT;

    const int tid  = threadIdx.x;
    const int wid  = tid >> 5, lane = tid & 31;
    const int wm   = wid & 3,  wn   = wid >> 2;
    const int bm = blockIdx.y * 128, bn = blockIdx.x * 128;

    const int g_row = (lane & 7) + ((lane >> 3) & 1) * 8;
    const int g_col = ((lane >> 4) & 1) * 8;

    const uint32_t uAh = smem_u32(sAh), uAl = smem_u32(sAl);
    const uint32_t uBh = smem_u32(sBh), uBl = smem_u32(sBl);

    const int lrow0 = tid >> 3, lc16 = tid & 7;

    float acc[2][8][4];
    #pragma unroll
    for (int mt = 0; mt < 2; mt++)
        #pragma unroll
        for (int nf = 0; nf < 8; nf++)
            #pragma unroll
            for (int r = 0; r < 4; r++) acc[mt][nf][r] = 0.f;

    uint4 pf[16];
    #pragma unroll
    for (int i = 0; i < 4; i++) {
        int row = lrow0 + i * 32;
        pf[i]      = *(const uint4*)&Ah[(size_t)(bm + row) * K + lc16*8];
        pf[4 + i]  = *(const uint4*)&Al[(size_t)(bm + row) * K + lc16*8];
        pf[8 + i]  = *(const uint4*)&Bh[(size_t)(bn + row) * K + lc16*8];
        pf[12 + i] = *(const uint4*)&Bl[(size_t)(bn + row) * K + lc16*8];
    }

    const int nchunks = K / 64;
    for (int kc = 0; kc < nchunks; kc++) {
        #pragma unroll
        for (int i = 0; i < 4; i++) {
            int soff = (lrow0 + i*32) * GROW + lc16 * 8;
            *(uint4*)&sAh[soff] = pf[i];
            *(uint4*)&sAl[soff] = pf[4 + i];
            *(uint4*)&sBh[soff] = pf[8 + i];
            *(uint4*)&sBl[soff] = pf[12 + i];
        }
        __syncthreads();

        if (kc + 1 < nchunks) {
            int k0 = (kc + 1) * 64;
            #pragma unroll
            for (int i = 0; i < 4; i++) {
                int row = lrow0 + i * 32;
                pf[i]      = *(const uint4*)&Ah[(size_t)(bm + row) * K + k0 + lc16*8];
                pf[4 + i]  = *(const uint4*)&Al[(size_t)(bm + row) * K + k0 + lc16*8];
                pf[8 + i]  = *(const uint4*)&Bh[(size_t)(bn + row) * K + k0 + lc16*8];
                pf[12 + i] = *(const uint4*)&Bl[(size_t)(bn + row) * K + k0 + lc16*8];
            }
        }

        #pragma unroll
        for (int ks = 0; ks < 4; ks++) {
            const int kcol = ks * 16 + g_col;
            uint32_t ah[2][4], al[2][4];
            #pragma unroll
            for (int mt = 0; mt < 2; mt++) {
                uint32_t off = ((wm*32 + mt*16 + g_row) * GROW + kcol) * 2;
                LDSM_X4(ah[mt][0], ah[mt][1], ah[mt][2], ah[mt][3], uAh + off);
                LDSM_X4(al[mt][0], al[mt][1], al[mt][2], al[mt][3], uAl + off);
            }
            uint32_t bh[8][2], bl[8][2];
            #pragma unroll
            for (int np = 0; np < 4; np++) {
                uint32_t off = ((wn*64 + np*16 + g_row) * GROW + kcol) * 2;
                uint32_t r0, r1, r2, r3;
                LDSM_X4(r0, r1, r2, r3, uBh + off);
                bh[2*np][0] = r0;   bh[2*np][1] = r2;
                bh[2*np+1][0] = r1; bh[2*np+1][1] = r3;
                LDSM_X4(r0, r1, r2, r3, uBl + off);
                bl[2*np][0] = r0;   bl[2*np][1] = r2;
                bl[2*np+1][0] = r1; bl[2*np+1][1] = r3;
            }
            #pragma unroll
            for (int mt = 0; mt < 2; mt++)
                #pragma unroll
                for (int nf = 0; nf < 8; nf++) {
                    MMA16816(acc[mt][nf], ah[mt], bh[nf]);
                    MMA16816(acc[mt][nf], ah[mt], bl[nf]);
                    MMA16816(acc[mt][nf], al[mt], bh[nf]);
                }
        }
        __syncthreads();
    }

    const int qrow = lane >> 2, qcol = (lane & 3) * 2;
    #pragma unroll
    for (int mt = 0; mt < 2; mt++) {
        int r0 = bm + wm*32 + mt*16 + qrow;
        #pragma unroll
        for (int nf = 0; nf < 8; nf++) {
            int col = bn + wn*64 + nf*8 + qcol;
            float2 vb = bias ? *(const float2*)&bias[col] : make_float2(0.f, 0.f);
            float2 o0, o1;
            o0.x = alpha * (acc[mt][nf][0] + vb.x);
            o0.y = alpha * (acc[mt][nf][1] + vb.y);
            o1.x = alpha * (acc[mt][nf][2] + vb.x);
            o1.y = alpha * (acc[mt][nf][3] + vb.y);
            size_t off0 = (size_t)r0 * N + col;
            size_t off1 = (size_t)(r0 + 8) * N + col;
            if (add) {
                float2 a0 = *(const float2*)&add[off0];
                float2 a1 = *(const float2*)&add[off1];
                o0.x += a0.x; o0.y += a0.y;
                o1.x += a1.x; o1.y += a1.y;
            }
            *(float2*)&C[off0] = o0;
            *(float2*)&C[off1] = o1;
        }
    }
}

// ---------------------------------------------------------------------------
// Attention v3: mma.sync bf16-split, 2-pass, P-fragment register reuse.
// Block = (b, h, 128 q rows). 8 warps x 16 q-rows, s-chunks of 128.
// ---------------------------------------------------------------------------
#define ATS 72   // bf16 row stride for q/k/v smem tiles (64 d + pad)

// load 128x64 fp32 tile rows -> split bf16 hi/lo smem tiles
__device__ __forceinline__ void load_split_tile(const float* __restrict__ src,
        __nv_bfloat16* dh, __nv_bfloat16* dl, int tid)
{
    const int r = tid >> 1, d0 = (tid & 1) * 32;
    const float* p = src + (size_t)r * Dq + d0;
    uint32_t hb[16], lb[16];
    #pragma unroll
    for (int i = 0; i < 8; i++) {
        float4 f = *(const float4*)(p + 4*i);
        float hx = __bfloat162float(__float2bfloat16_rn(f.x));
        float hy = __bfloat162float(__float2bfloat16_rn(f.y));
        float hz = __bfloat162float(__float2bfloat16_rn(f.z));
        float hw = __bfloat162float(__float2bfloat16_rn(f.w));
        hb[2*i]   = bf2x(hx, hy);
        hb[2*i+1] = bf2x(hz, hw);
        lb[2*i]   = bf2x(f.x - hx, f.y - hy);
        lb[2*i+1] = bf2x(f.z - hz, f.w - hw);
    }
    uint4* oh = (uint4*)(dh + (size_t)r * ATS + d0);
    uint4* ol = (uint4*)(dl + (size_t)r * ATS + d0);
    #pragma unroll
    for (int i = 0; i < 4; i++) {
        oh[i] = make_uint4(hb[4*i], hb[4*i+1], hb[4*i+2], hb[4*i+3]);
        ol[i] = make_uint4(lb[4*i], lb[4*i+1], lb[4*i+2], lb[4*i+3]);
    }
}

// S = q @ kr^T for one 16x128 warp tile, 3-term bf16 split, fp32 acc
__device__ __forceinline__ void s_mma(uint32_t uqh, uint32_t uql,
        uint32_t ukh, uint32_t ukl, int wid, int g_row, int g_col,
        float acc[16][4])
{
    #pragma unroll
    for (int nf = 0; nf < 16; nf++) {
        acc[nf][0] = 0.f; acc[nf][1] = 0.f; acc[nf][2] = 0.f; acc[nf][3] = 0.f;
    }
    #pragma unroll
    for (int ks = 0; ks < 4; ks++) {
        uint32_t ah[4], al[4];
        uint32_t aoff = (uint32_t)(((wid*16 + g_row) * ATS + ks*16 + g_col) * 2);
        LDSM_X4(ah[0], ah[1], ah[2], ah[3], uqh + aoff);
        LDSM_X4(al[0], al[1], al[2], al[3], uql + aoff);
        #pragma unroll
        for (int np = 0; np < 8; np++) {
            uint32_t boff = (uint32_t)(((np*16 + g_row) * ATS + ks*16 + g_col) * 2);
            uint32_t r0, r1, r2, r3, s0, s1, s2, s3;
            LDSM_X4(r0, r1, r2, r3, ukh + boff);
            LDSM_X4(s0, s1, s2, s3, ukl + boff);
            uint32_t b0[2] = {r0, r2}, b1[2] = {r1, r3};
            uint32_t c0[2] = {s0, s2}, c1[2] = {s1, s3};
            MMA16816(acc[2*np],   ah, b0);
            MMA16816(acc[2*np],   al, b0);
            MMA16816(acc[2*np],   ah, c0);
            MMA16816(acc[2*np+1], ah, b1);
            MMA16816(acc[2*np+1], al, b1);
            MMA16816(acc[2*np+1], ah, c1);
        }
    }
}

__global__ __launch_bounds__(256, 1)
void attn3_kernel(const float* __restrict__ q, const float* __restrict__ kr,
                  const float* __restrict__ v, const int* __restrict__ mask,
                  float* __restrict__ probs,
                  __nv_bfloat16* __restrict__ ctx_h, __nv_bfloat16* __restrict__ ctx_l)
{
    extern __shared__ __nv_bfloat16 sm_[];
    __nv_bfloat16* qh = sm_;
    __nv_bfloat16* ql = qh + 128*ATS;
    __nv_bfloat16* kh = ql + 128*ATS;
    __nv_bfloat16* kl = kh + 128*ATS;
    __nv_bfloat16* vh = kl + 128*ATS;
    __nv_bfloat16* vl = vh + 128*ATS;
    int* msk = (int*)(vl + 128*ATS);

    const int t0 = blockIdx.x * 128, h = blockIdx.y, b = blockIdx.z;
    const int tid = threadIdx.x, wid = tid >> 5, lane = tid & 31;
    const int qrow = lane >> 2, qc2 = (lane & 3) * 2;
    const int g_row = (lane & 7) + ((lane >> 3) & 1) * 8;
    const int g_col = ((lane >> 4) & 1) * 8;

    const uint32_t uqh = smem_u32(qh), uql = smem_u32(ql);
    const uint32_t ukh = smem_u32(kh), ukl = smem_u32(kl);
    const uint32_t uvh = smem_u32(vh), uvl = smem_u32(vl);

    const float* qbase  = q  + ((size_t)(b*Tq + t0)) * Dq + h*DHq;
    const float* krbase = kr + ((size_t)(b*Tq)) * Dq + h*DHq;
    const float* vbase  = v  + ((size_t)(b*Tq)) * Dq + h*DHq;

    load_split_tile(qbase, qh, ql, tid);
    for (int s = tid; s < Tq; s += 256) msk[s] = mask[b*Tq + s];

    // =================== PASS 1: row max + sumexp (registers only) =========
    float m0 = -1e30f, m1 = -1e30f, l0 = 0.f, l1 = 0.f;

    for (int st = 0; st < 8; st++) {
        __syncthreads();
        load_split_tile(krbase + (size_t)(st*128) * Dq, kh, kl, tid);
        __syncthreads();

        float acc[16][4];
        s_mma(uqh, uql, ukh, ukl, wid, g_row, g_col, acc);

        int s0 = st * 128;
        float cm0 = -1e30f, cm1 = -1e30f;
        #pragma unroll
        for (int nf = 0; nf < 16; nf++) {
            int col = s0 + nf*8 + qc2;
            int k0 = msk[col], k1 = msk[col + 1];
            acc[nf][0] = k0 ? acc[nf][0] : -1e9f;
            acc[nf][1] = k1 ? acc[nf][1] : -1e9f;
            acc[nf][2] = k0 ? acc[nf][2] : -1e9f;
            acc[nf][3] = k1 ? acc[nf][3] : -1e9f;
            cm0 = fmaxf(cm0, fmaxf(acc[nf][0], acc[nf][1]));
            cm1 = fmaxf(cm1, fmaxf(acc[nf][2], acc[nf][3]));
        }
        cm0 = fmaxf(cm0, __shfl_xor_sync(0xffffffffu, cm0, 1));
        cm0 = fmaxf(cm0, __shfl_xor_sync(0xffffffffu, cm0, 2));
        cm1 = fmaxf(cm1, __shfl_xor_sync(0xffffffffu, cm1, 1));
        cm1 = fmaxf(cm1, __shfl_xor_sync(0xffffffffu, cm1, 2));
        float nm0 = fmaxf(m0, cm0), nm1 = fmaxf(m1, cm1);
        float sa0 = 0.f, sa1 = 0.f;
        #pragma unroll
        for (int nf = 0; nf < 16; nf++) {
            sa0 += __expf(acc[nf][0] - nm0) + __expf(acc[nf][1] - nm0);
            sa1 += __expf(acc[nf][2] - nm1) + __expf(acc[nf][3] - nm1);
        }
        sa0 += __shfl_xor_sync(0xffffffffu, sa0, 1);
        sa0 += __shfl_xor_sync(0xffffffffu, sa0, 2);
        sa1 += __shfl_xor_sync(0xffffffffu, sa1, 1);
        sa1 += __shfl_xor_sync(0xffffffffu, sa1, 2);
        l0 = l0 * __expf(m0 - nm0) + sa0;  m0 = nm0;
        l1 = l1 * __expf(m1 - nm1) + sa1;  m1 = nm1;
    }

    const float M0 = m0, M1 = m1;
    const float iL0 = 1.0f / l0, iL1 = 1.0f / l1;

    // =================== PASS 2: probs + ctx ===============================
    float cacc[8][4];
    #pragma unroll
    for (int nf = 0; nf < 8; nf++) {
        cacc[nf][0] = 0.f; cacc[nf][1] = 0.f; cacc[nf][2] = 0.f; cacc[nf][3] = 0.f;
    }

    const size_t prow0 = ((size_t)((b*Hq + h)*Tq) + t0 + wid*16 + qrow) * Tq;

    for (int st = 0; st < 8; st++) {
        __syncthreads();
        load_split_tile(krbase + (size_t)(st*128) * Dq, kh, kl, tid);
        load_split_tile(vbase  + (size_t)(st*128) * Dq, vh, vl, tid);
        __syncthreads();

        float acc[16][4];
        s_mma(uqh, uql, ukh, ukl, wid, g_row, g_col, acc);

        int s0 = st * 128;
        uint32_t aPh[8][4], aPl[8][4];
        #pragma unroll
        for (int j = 0; j < 8; j++) {
            float p[8];
            #pragma unroll
            for (int u = 0; u < 2; u++) {
                int nf = 2*j + u;
                int col = s0 + nf*8 + qc2;
                int k0 = msk[col], k1 = msk[col + 1];
                float f0 = k0 ? acc[nf][0] : -1e9f;
                float f1 = k1 ? acc[nf][1] : -1e9f;
                float f2 = k0 ? acc[nf][2] : -1e9f;
                float f3 = k1 ? acc[nf][3] : -1e9f;
                float p0 = __expf(f0 - M0) * iL0;
                float p1 = __expf(f1 - M0) * iL0;
                float p2 = __expf(f2 - M1) * iL1;
                float p3 = __expf(f3 - M1) * iL1;
                *(float2*)&probs[prow0 + col]          = make_float2(p0, p1);
                *(float2*)&probs[prow0 + 8*Tq + col]   = make_float2(p2, p3);
                p[u*4 + 0] = p0; p[u*4 + 1] = p1; p[u*4 + 2] = p2; p[u*4 + 3] = p3;
            }
            // pack P frags: a0=(r,k0k1), a1=(r+8,k0k1), a2=(r,k8k9), a3=(r+8,k8k9)
            float h0 = __bfloat162float(__float2bfloat16_rn(p[0]));
            float h1 = __bfloat162float(__float2bfloat16_rn(p[1]));
            float h2 = __bfloat162float(__float2bfloat16_rn(p[2]));
            float h3 = __bfloat162float(__float2bfloat16_rn(p[3]));
            float h4 = __bfloat162float(__float2bfloat16_rn(p[4]));
            float h5 = __bfloat162float(__float2bfloat16_rn(p[5]));
            float h6 = __bfloat162float(__float2bfloat16_rn(p[6]));
            float h7 = __bfloat162float(__float2bfloat16_rn(p[7]));
            aPh[j][0] = bf2x(h0, h1);            aPh[j][1] = bf2x(h2, h3);
            aPh[j][2] = bf2x(h4, h5);            aPh[j][3] = bf2x(h6, h7);
            aPl[j][0] = bf2x(p[0]-h0, p[1]-h1);  aPl[j][1] = bf2x(p[2]-h2, p[3]-h3);
            aPl[j][2] = bf2x(p[4]-h4, p[5]-h5);  aPl[j][3] = bf2x(p[6]-h6, p[7]-h7);
        }

        // ctx += P @ V  (V via ldmatrix.trans from [s][d] tiles)
        #pragma unroll
        for (int ks = 0; ks < 8; ks++) {
            uint32_t bh[8][2], bl[8][2];
            #pragma unroll
            for (int npv = 0; npv < 4; npv++) {
                uint32_t off = (uint32_t)(((ks*16 + g_row) * ATS + npv*16 + g_col) * 2);
                uint32_t r0, r1, r2, r3;
                LDSM_T_X4(r0, r1, r2, r3, uvh + off);
                bh[2*npv][0] = r0;   bh[2*npv][1] = r1;
                bh[2*npv+1][0] = r2; bh[2*npv+1][1] = r3;
                LDSM_T_X4(r0, r1, r2, r3, uvl + off);
                bl[2*npv][0] = r0;   bl[2*npv][1] = r1;
                bl[2*npv+1][0] = r2; bl[2*npv+1][1] = r3;
            }
            #pragma unroll
            for (int nf = 0; nf < 8; nf++) {
                MMA16816(cacc[nf], aPh[ks], bh[nf]);
                MMA16816(cacc[nf], aPh[ks], bl[nf]);
                MMA16816(cacc[nf], aPl[ks], bh[nf]);
            }
        }
    }

    // write ctx as bf16 hi/lo split (feeds the Wo GEMM directly)
    {
        int r = t0 + wid*16 + qrow;
        size_t base0 = ((size_t)(b*Tq + r)) * Dq + h*DHq;
        size_t base1 = ((size_t)(b*Tq + r + 8)) * Dq + h*DHq;
        #pragma unroll
        for (int nf = 0; nf < 8; nf++) {
            int col = nf*8 + qc2;
            float h0 = __bfloat162float(__float2bfloat16_rn(cacc[nf][0]));
            float h1 = __bfloat162float(__float2bfloat16_rn(cacc[nf][1]));
            float h2 = __bfloat162float(__float2bfloat16_rn(cacc[nf][2]));
            float h3 = __bfloat162float(__float2bfloat16_rn(cacc[nf][3]));
            *(uint32_t*)&ctx_h[base0 + col] = bf2x(h0, h1);
            *(uint32_t*)&ctx_l[base0 + col] = bf2x(cacc[nf][0]-h0, cacc[nf][1]-h1);
            *(uint32_t*)&ctx_h[base1 + col] = bf2x(h2, h3);
            *(uint32_t*)&ctx_l[base1 + col] = bf2x(cacc[nf][2]-h2, cacc[nf][3]-h3);
        }
    }
}

#define ATTN_SMEM (6*128*ATS*2 + Tq*4)

// ---------------------------------------------------------------------------
extern "C" void kernel_launch(void* const* d_in, const int* in_sizes, int n_in,
                              void* d_out, int out_size)
{
    const float* query   = (const float*)d_in[0];
    const float* key     = (const float*)d_in[1];
    const float* value   = (const float*)d_in[2];
    const float* rel_pos = (const float*)d_in[3];
    const int*   kpm     = (const int*)  d_in[4];
    const float* qn_g = (const float*)d_in[5];
    const float* qn_b = (const float*)d_in[6];
    const float* kn_g = (const float*)d_in[7];
    const float* kn_b = (const float*)d_in[8];
    const float* vn_g = (const float*)d_in[9];
    const float* vn_b = (const float*)d_in[10];
    const float* Wq = (const float*)d_in[11];
    const float* bq = (const float*)d_in[12];
    const float* Wk = (const float*)d_in[13];
    const float* bk = (const float*)d_in[14];
    const float* Wv = (const float*)d_in[15];
    const float* bv = (const float*)d_in[16];
    const float* Wr = (const float*)d_in[17];
    const float* Wo = (const float*)d_in[18];
    const float* bo = (const float*)d_in[19];

    float* out   = (float*)d_out;
    float* probs = out + OUT_ELEMS;

    float *p_q, *p_k, *p_v;
    cudaGetSymbolAddress((void**)&p_q, g_q);
    cudaGetSymbolAddress((void**)&p_k, g_k);
    cudaGetSymbolAddress((void**)&p_v, g_v);

    __nv_bfloat16 *lnq_h,*lnq_l,*lnk_h,*lnk_l,*lnv_h,*lnv_l,*rp_h,*rp_l,*ctx_h,*ctx_l;
    __nv_bfloat16 *wq_h,*wq_l,*wk_h,*wk_l,*wv_h,*wv_l,*wr_h,*wr_l,*wo_h,*wo_l;
    cudaGetSymbolAddress((void**)&lnq_h, g_lnq_h); cudaGetSymbolAddress((void**)&lnq_l, g_lnq_l);
    cudaGetSymbolAddress((void**)&lnk_h, g_lnk_h); cudaGetSymbolAddress((void**)&lnk_l, g_lnk_l);
    cudaGetSymbolAddress((void**)&lnv_h, g_lnv_h); cudaGetSymbolAddress((void**)&lnv_l, g_lnv_l);
    cudaGetSymbolAddress((void**)&rp_h,  g_rp_h);  cudaGetSymbolAddress((void**)&rp_l,  g_rp_l);
    cudaGetSymbolAddress((void**)&ctx_h, g_ctx_h); cudaGetSymbolAddress((void**)&ctx_l, g_ctx_l);
    cudaGetSymbolAddress((void**)&wq_h, g_wq_h);   cudaGetSymbolAddress((void**)&wq_l, g_wq_l);
    cudaGetSymbolAddress((void**)&wk_h, g_wk_h);   cudaGetSymbolAddress((void**)&wk_l, g_wk_l);
    cudaGetSymbolAddress((void**)&wv_h, g_wv_h);   cudaGetSymbolAddress((void**)&wv_l, g_wv_l);
    cudaGetSymbolAddress((void**)&wr_h, g_wr_h);   cudaGetSymbolAddress((void**)&wr_l, g_wr_l);
    cudaGetSymbolAddress((void**)&wo_h, g_wo_h);   cudaGetSymbolAddress((void**)&wo_l, g_wo_l);

    cudaFuncSetAttribute(mma_gemm_kernel, cudaFuncAttributeMaxDynamicSharedMemorySize, GSM_BYTES);
    cudaFuncSetAttribute(attn3_kernel, cudaFuncAttributeMaxDynamicSharedMemorySize, ATTN_SMEM);

    // 1) weight transpose + split (5x)
    dim3 wgrid(Dq/32, Dq/32);
    wsplit_kernel<<<wgrid, 256>>>(Wq, wq_h, wq_l);
    wsplit_kernel<<<wgrid, 256>>>(Wk, wk_h, wk_l);
    wsplit_kernel<<<wgrid, 256>>>(Wv, wv_h, wv_l);
    wsplit_kernel<<<wgrid, 256>>>(Wr, wr_h, wr_l);
    wsplit_kernel<<<wgrid, 256>>>(Wo, wo_h, wo_l);

    // 2) LayerNorms with bf16 split output + rel_pos split
    ln_split_kernel<<<Mrows, 256>>>(query, qn_g, qn_b, lnq_h, lnq_l);
    ln_split_kernel<<<Mrows, 256>>>(key,   kn_g, kn_b, lnk_h, lnk_l);
    ln_split_kernel<<<Mrows, 256>>>(value, vn_g, vn_b, lnv_h, lnv_l);
    fsplit_kernel<<<(Mrows*Dq)/1024, 256>>>(rel_pos, rp_h, rp_l);

    // 3) projection GEMMs (tensor cores)
    dim3 ggrid(Dq/128, Mrows/128);
    mma_gemm_kernel<<<ggrid, 256, GSM_BYTES>>>(lnq_h, lnq_l, wq_h, wq_l, bq, nullptr, 0.125f, p_q, Mrows, Dq, Dq);
    mma_gemm_kernel<<<ggrid, 256, GSM_BYTES>>>(lnk_h, lnk_l, wk_h, wk_l, bk, nullptr, 1.0f,   p_k, Mrows, Dq, Dq);
    mma_gemm_kernel<<<ggrid, 256, GSM_BYTES>>>(lnv_h, lnv_l, wv_h, wv_l, bv, nullptr, 1.0f,   p_v, Mrows, Dq, Dq);
    mma_gemm_kernel<<<ggrid, 256, GSM_BYTES>>>(rp_h,  rp_l,  wr_h, wr_l, nullptr, p_k, 0.1f,  p_k, Mrows, Dq, Dq);

    // 4) attention (tensor cores) -> probs + bf16-split ctx
    dim3 agrid(Tq/128, Hq, Bq);
    attn3_kernel<<<agrid, 256, ATTN_SMEM>>>(p_q, p_k, p_v, kpm, probs, ctx_h, ctx_l);

    // 5) out = ctx@Wo + bo
    mma_gemm_kernel<<<ggrid, 256, GSM_BYTES>>>(ctx_h, ctx_l, wo_h, wo_l, bo, nullptr, 1.0f, out, Mrows, Dq, Dq);
}

// round 7
// speedup vs baseline: 2.8109x; 1.1218x over previous
#include <cuda_runtime.h>
#include <cuda_bf16.h>
#include <math.h>
#include <cstdint>

// Problem constants
#define Bq   4
#define Tq   1024
#define Dq   1024
#define Hq   16
#define DHq  64
#define Mrows (Bq*Tq)
#define OUT_ELEMS ((size_t)Mrows*Dq)

// ---------------- device scratch (no runtime allocation) -------------------
__device__ float g_k[Mrows*Dq];          // fp32 k (pre rel_pos merge)
__device__ float2 g_ml[Bq*Hq*Tq];        // per-row (M, 1/L)

// bf16 split operand buffers
__device__ __nv_bfloat16 g_lnq_h[Mrows*Dq], g_lnq_l[Mrows*Dq];
__device__ __nv_bfloat16 g_lnk_h[Mrows*Dq], g_lnk_l[Mrows*Dq];
__device__ __nv_bfloat16 g_lnv_h[Mrows*Dq], g_lnv_l[Mrows*Dq];
__device__ __nv_bfloat16 g_rp_h [Mrows*Dq], g_rp_l [Mrows*Dq];
__device__ __nv_bfloat16 g_qs_h [Mrows*Dq], g_qs_l [Mrows*Dq];
__device__ __nv_bfloat16 g_kr_h [Mrows*Dq], g_kr_l [Mrows*Dq];
__device__ __nv_bfloat16 g_vs_h [Mrows*Dq], g_vs_l [Mrows*Dq];
__device__ __nv_bfloat16 g_ctx_h[Mrows*Dq], g_ctx_l[Mrows*Dq];
// transposed+split weights [N,K]
__device__ __nv_bfloat16 g_wq_h[Dq*Dq], g_wq_l[Dq*Dq];
__device__ __nv_bfloat16 g_wk_h[Dq*Dq], g_wk_l[Dq*Dq];
__device__ __nv_bfloat16 g_wv_h[Dq*Dq], g_wv_l[Dq*Dq];
__device__ __nv_bfloat16 g_wr_h[Dq*Dq], g_wr_l[Dq*Dq];
__device__ __nv_bfloat16 g_wo_h[Dq*Dq], g_wo_l[Dq*Dq];

// ------------------------- mma.sync / ldmatrix helpers ---------------------
__device__ __forceinline__ uint32_t smem_u32(const void* p) {
    uint32_t a;
    asm("{ .reg .u64 t; cvta.to.shared.u64 t, %1; cvt.u32.u64 %0, t; }"
        : "=r"(a) : "l"(p));
    return a;
}
#define LDSM_X4(r0, r1, r2, r3, addr)                                        \
    asm volatile("ldmatrix.sync.aligned.m8n8.x4.shared.b16 {%0,%1,%2,%3}, [%4];" \
        : "=r"(r0), "=r"(r1), "=r"(r2), "=r"(r3) : "r"(addr))

#define LDSM_T_X4(r0, r1, r2, r3, addr)                                      \
    asm volatile("ldmatrix.sync.aligned.m8n8.x4.trans.shared.b16 {%0,%1,%2,%3}, [%4];" \
        : "=r"(r0), "=r"(r1), "=r"(r2), "=r"(r3) : "r"(addr))

#define MMA16816(c, a, b)                                                    \
    asm volatile("mma.sync.aligned.m16n8k16.row.col.f32.bf16.bf16.f32 "      \
        "{%0,%1,%2,%3}, {%4,%5,%6,%7}, {%8,%9}, {%0,%1,%2,%3};"              \
        : "+f"((c)[0]), "+f"((c)[1]), "+f"((c)[2]), "+f"((c)[3])             \
        : "r"((a)[0]), "r"((a)[1]), "r"((a)[2]), "r"((a)[3]),                \
          "r"((b)[0]), "r"((b)[1]))

// pack two fp32 -> bf16x2 reg (first arg in low half)
__device__ __forceinline__ uint32_t bf2x(float lo, float hi) {
    uint32_t r;
    asm("cvt.rn.bf16x2.f32 %0, %1, %2;" : "=r"(r) : "f"(hi), "f"(lo));
    return r;
}

// ---------------------------------------------------------------------------
// LayerNorm over last dim (1024); outputs bf16 hi/lo split.
// ---------------------------------------------------------------------------
__global__ __launch_bounds__(256)
void ln_split_kernel(const float* __restrict__ x, const float* __restrict__ gamma,
                     const float* __restrict__ beta,
                     __nv_bfloat16* __restrict__ hi, __nv_bfloat16* __restrict__ lo)
{
    int row = blockIdx.x;
    int tid = threadIdx.x;
    const float4* xr = reinterpret_cast<const float4*>(x + (size_t)row * Dq);
    float4 v = xr[tid];
    float s  = v.x + v.y + v.z + v.w;
    float s2 = v.x*v.x + v.y*v.y + v.z*v.z + v.w*v.w;
    #pragma unroll
    for (int o = 16; o; o >>= 1) {
        s  += __shfl_xor_sync(0xffffffffu, s,  o);
        s2 += __shfl_xor_sync(0xffffffffu, s2, o);
    }
    __shared__ float ws[8], ws2[8], stats[2];
    int w = tid >> 5, lane = tid & 31;
    if (lane == 0) { ws[w] = s; ws2[w] = s2; }
    __syncthreads();
    if (tid == 0) {
        float ts = 0.f, ts2 = 0.f;
        #pragma unroll
        for (int i = 0; i < 8; i++) { ts += ws[i]; ts2 += ws2[i]; }
        float mu  = ts * (1.0f / Dq);
        float var = ts2 * (1.0f / Dq) - mu * mu;
        stats[0] = mu;
        stats[1] = rsqrtf(var + 1e-5f);
    }
    __syncthreads();
    float mu = stats[0], rstd = stats[1];
    float4 g = reinterpret_cast<const float4*>(gamma)[tid];
    float4 b = reinterpret_cast<const float4*>(beta)[tid];
    float o4[4];
    o4[0] = (v.x - mu) * rstd * g.x + b.x;
    o4[1] = (v.y - mu) * rstd * g.y + b.y;
    o4[2] = (v.z - mu) * rstd * g.z + b.z;
    o4[3] = (v.w - mu) * rstd * g.w + b.w;
    __nv_bfloat16 h4[4], l4[4];
    #pragma unroll
    for (int i = 0; i < 4; i++) {
        h4[i] = __float2bfloat16_rn(o4[i]);
        l4[i] = __float2bfloat16_rn(o4[i] - __bfloat162float(h4[i]));
    }
    *(ulonglong1*)&hi[(size_t)row * Dq + tid*4] = *(ulonglong1*)h4;
    *(ulonglong1*)&lo[(size_t)row * Dq + tid*4] = *(ulonglong1*)l4;
}

// plain fp32 -> bf16 hi/lo split (rel_pos)
__global__ __launch_bounds__(256)
void fsplit_kernel(const float* __restrict__ x,
                   __nv_bfloat16* __restrict__ hi, __nv_bfloat16* __restrict__ lo)
{
    size_t i = ((size_t)blockIdx.x * 256 + threadIdx.x) * 4;
    float4 v = *(const float4*)&x[i];
    float o4[4] = {v.x, v.y, v.z, v.w};
    __nv_bfloat16 h4[4], l4[4];
    #pragma unroll
    for (int j = 0; j < 4; j++) {
        h4[j] = __float2bfloat16_rn(o4[j]);
        l4[j] = __float2bfloat16_rn(o4[j] - __bfloat162float(h4[j]));
    }
    *(ulonglong1*)&hi[i] = *(ulonglong1*)h4;
    *(ulonglong1*)&lo[i] = *(ulonglong1*)l4;
}

// 5 weights: W [K,N] -> WT [N,K] bf16 hi/lo split, one launch
struct WSplitArgs {
    const float* W[5];
    __nv_bfloat16 *H[5], *L[5];
};
__global__ __launch_bounds__(256)
void wsplit5_kernel(WSplitArgs a)
{
    __shared__ float t[32][33];
    const float* W = a.W[blockIdx.z];
    __nv_bfloat16* hi = a.H[blockIdx.z];
    __nv_bfloat16* lo = a.L[blockIdx.z];
    int tx = threadIdx.x & 31, ty = threadIdx.x >> 5;
    int nb = blockIdx.x * 32, kb = blockIdx.y * 32;
    #pragma unroll
    for (int i = 0; i < 32; i += 8)
        t[ty+i][tx] = W[(size_t)(kb + ty + i) * Dq + nb + tx];
    __syncthreads();
    #pragma unroll
    for (int i = 0; i < 32; i += 8) {
        float v = t[tx][ty+i];
        __nv_bfloat16 h = __float2bfloat16_rn(v);
        size_t off = (size_t)(nb + ty + i) * Dq + kb + tx;
        hi[off] = h;
        lo[off] = __float2bfloat16_rn(v - __bfloat162float(h));
    }
}

// ---------------------------------------------------------------------------
// mma.sync GEMM, 3xBF16 emulated fp32.
//   o = alpha*(Ah@B^T + bias) + add;  written to fp32 C, or bf16 split Ch/Cl.
// ---------------------------------------------------------------------------
#define GROW 72
#define GT   (128*GROW)
#define GSM_BYTES (4*GT*2)

__global__ __launch_bounds__(256, 1)
void mma_gemm_kernel(const __nv_bfloat16* __restrict__ Ah, const __nv_bfloat16* __restrict__ Al,
                     const __nv_bfloat16* __restrict__ Bh, const __nv_bfloat16* __restrict__ Bl,
                     const float* __restrict__ bias, const float* __restrict__ add,
                     float alpha, float* __restrict__ C,
                     __nv_bfloat16* __restrict__ Ch, __nv_bfloat16* __restrict__ Cl,
                     int M, int N, int K)
{
    extern __shared__ __nv_bfloat16 gsm[];
    __nv_bfloat16* sAh = gsm;
    __nv_bfloat16* sAl = gsm + GT;
    __nv_bfloat16* sBh = gsm + 2*GT;
    __nv_bfloat16* sBl = gsm + 3*GT;

    const int tid  = threadIdx.x;
    const int wid  = tid >> 5, lane = tid & 31;
    const int wm   = wid & 3,  wn   = wid >> 2;
    const int bm = blockIdx.y * 128, bn = blockIdx.x * 128;

    const int g_row = (lane & 7) + ((lane >> 3) & 1) * 8;
    const int g_col = ((lane >> 4) & 1) * 8;

    const uint32_t uAh = smem_u32(sAh), uAl = smem_u32(sAl);
    const uint32_t uBh = smem_u32(sBh), uBl = smem_u32(sBl);

    const int lrow0 = tid >> 3, lc16 = tid & 7;

    float acc[2][8][4];
    #pragma unroll
    for (int mt = 0; mt < 2; mt++)
        #pragma unroll
        for (int nf = 0; nf < 8; nf++)
            #pragma unroll
            for (int r = 0; r < 4; r++) acc[mt][nf][r] = 0.f;

    uint4 pf[16];
    #pragma unroll
    for (int i = 0; i < 4; i++) {
        int row = lrow0 + i * 32;
        pf[i]      = *(const uint4*)&Ah[(size_t)(bm + row) * K + lc16*8];
        pf[4 + i]  = *(const uint4*)&Al[(size_t)(bm + row) * K + lc16*8];
        pf[8 + i]  = *(const uint4*)&Bh[(size_t)(bn + row) * K + lc16*8];
        pf[12 + i] = *(const uint4*)&Bl[(size_t)(bn + row) * K + lc16*8];
    }

    const int nchunks = K / 64;
    for (int kc = 0; kc < nchunks; kc++) {
        #pragma unroll
        for (int i = 0; i < 4; i++) {
            int soff = (lrow0 + i*32) * GROW + lc16 * 8;
            *(uint4*)&sAh[soff] = pf[i];
            *(uint4*)&sAl[soff] = pf[4 + i];
            *(uint4*)&sBh[soff] = pf[8 + i];
            *(uint4*)&sBl[soff] = pf[12 + i];
        }
        __syncthreads();

        if (kc + 1 < nchunks) {
            int k0 = (kc + 1) * 64;
            #pragma unroll
            for (int i = 0; i < 4; i++) {
                int row = lrow0 + i * 32;
                pf[i]      = *(const uint4*)&Ah[(size_t)(bm + row) * K + k0 + lc16*8];
                pf[4 + i]  = *(const uint4*)&Al[(size_t)(bm + row) * K + k0 + lc16*8];
                pf[8 + i]  = *(const uint4*)&Bh[(size_t)(bn + row) * K + k0 + lc16*8];
                pf[12 + i] = *(const uint4*)&Bl[(size_t)(bn + row) * K + k0 + lc16*8];
            }
        }

        #pragma unroll
        for (int ks = 0; ks < 4; ks++) {
            const int kcol = ks * 16 + g_col;
            uint32_t ah[2][4], al[2][4];
            #pragma unroll
            for (int mt = 0; mt < 2; mt++) {
                uint32_t off = ((wm*32 + mt*16 + g_row) * GROW + kcol) * 2;
                LDSM_X4(ah[mt][0], ah[mt][1], ah[mt][2], ah[mt][3], uAh + off);
                LDSM_X4(al[mt][0], al[mt][1], al[mt][2], al[mt][3], uAl + off);
            }
            uint32_t bh[8][2], bl[8][2];
            #pragma unroll
            for (int np = 0; np < 4; np++) {
                uint32_t off = ((wn*64 + np*16 + g_row) * GROW + kcol) * 2;
                uint32_t r0, r1, r2, r3;
                LDSM_X4(r0, r1, r2, r3, uBh + off);
                bh[2*np][0] = r0;   bh[2*np][1] = r2;
                bh[2*np+1][0] = r1; bh[2*np+1][1] = r3;
                LDSM_X4(r0, r1, r2, r3, uBl + off);
                bl[2*np][0] = r0;   bl[2*np][1] = r2;
                bl[2*np+1][0] = r1; bl[2*np+1][1] = r3;
            }
            #pragma unroll
            for (int mt = 0; mt < 2; mt++)
                #pragma unroll
                for (int nf = 0; nf < 8; nf++) {
                    MMA16816(acc[mt][nf], ah[mt], bh[nf]);
                    MMA16816(acc[mt][nf], ah[mt], bl[nf]);
                    MMA16816(acc[mt][nf], al[mt], bh[nf]);
                }
        }
        __syncthreads();
    }

    const int qrow = lane >> 2, qcol = (lane & 3) * 2;
    #pragma unroll
    for (int mt = 0; mt < 2; mt++) {
        int r0 = bm + wm*32 + mt*16 + qrow;
        #pragma unroll
        for (int nf = 0; nf < 8; nf++) {
            int col = bn + wn*64 + nf*8 + qcol;
            float2 vb = bias ? *(const float2*)&bias[col] : make_float2(0.f, 0.f);
            float2 o0, o1;
            o0.x = alpha * (acc[mt][nf][0] + vb.x);
            o0.y = alpha * (acc[mt][nf][1] + vb.y);
            o1.x = alpha * (acc[mt][nf][2] + vb.x);
            o1.y = alpha * (acc[mt][nf][3] + vb.y);
            size_t off0 = (size_t)r0 * N + col;
            size_t off1 = (size_t)(r0 + 8) * N + col;
            if (add) {
                float2 a0 = *(const float2*)&add[off0];
                float2 a1 = *(const float2*)&add[off1];
                o0.x += a0.x; o0.y += a0.y;
                o1.x += a1.x; o1.y += a1.y;
            }
            if (C) {
                *(float2*)&C[off0] = o0;
                *(float2*)&C[off1] = o1;
            } else {
                float h0 = __bfloat162float(__float2bfloat16_rn(o0.x));
                float h1 = __bfloat162float(__float2bfloat16_rn(o0.y));
                float h2 = __bfloat162float(__float2bfloat16_rn(o1.x));
                float h3 = __bfloat162float(__float2bfloat16_rn(o1.y));
                *(uint32_t*)&Ch[off0] = bf2x(h0, h1);
                *(uint32_t*)&Cl[off0] = bf2x(o0.x - h0, o0.y - h1);
                *(uint32_t*)&Ch[off1] = bf2x(h2, h3);
                *(uint32_t*)&Cl[off1] = bf2x(o1.x - h2, o1.y - h3);
            }
        }
    }
}

// ---------------------------------------------------------------------------
// Attention v4: single-pass flash, bf16-presplit inputs, raw S to gmem,
// per-row (M, 1/L) out; probs normalized by a follow-up streaming kernel.
// Block = (b, h, 128 q rows). 8 warps x 16 q-rows, s-chunks of 128.
// ---------------------------------------------------------------------------
#define ATS 72   // bf16 row stride for q/k/v smem tiles

// S = q @ kr^T for one 16x128 warp tile, 3-term bf16 split, fp32 acc
__device__ __forceinline__ void s_mma(uint32_t uqh, uint32_t uql,
        uint32_t ukh, uint32_t ukl, int wid, int g_row, int g_col,
        float acc[16][4])
{
    #pragma unroll
    for (int nf = 0; nf < 16; nf++) {
        acc[nf][0] = 0.f; acc[nf][1] = 0.f; acc[nf][2] = 0.f; acc[nf][3] = 0.f;
    }
    #pragma unroll
    for (int ks = 0; ks < 4; ks++) {
        uint32_t ah[4], al[4];
        uint32_t aoff = (uint32_t)(((wid*16 + g_row) * ATS + ks*16 + g_col) * 2);
        LDSM_X4(ah[0], ah[1], ah[2], ah[3], uqh + aoff);
        LDSM_X4(al[0], al[1], al[2], al[3], uql + aoff);
        #pragma unroll
        for (int np = 0; np < 8; np++) {
            uint32_t boff = (uint32_t)(((np*16 + g_row) * ATS + ks*16 + g_col) * 2);
            uint32_t r0, r1, r2, r3, s0, s1, s2, s3;
            LDSM_X4(r0, r1, r2, r3, ukh + boff);
            LDSM_X4(s0, s1, s2, s3, ukl + boff);
            uint32_t b0[2] = {r0, r2}, b1[2] = {r1, r3};
            uint32_t c0[2] = {s0, s2}, c1[2] = {s1, s3};
            MMA16816(acc[2*np],   ah, b0);
            MMA16816(acc[2*np],   al, b0);
            MMA16816(acc[2*np],   ah, c0);
            MMA16816(acc[2*np+1], ah, b1);
            MMA16816(acc[2*np+1], al, b1);
            MMA16816(acc[2*np+1], ah, c1);
        }
    }
}

__global__ __launch_bounds__(256, 1)
void attn4_kernel(const __nv_bfloat16* __restrict__ qh_g, const __nv_bfloat16* __restrict__ ql_g,
                  const __nv_bfloat16* __restrict__ kh_g, const __nv_bfloat16* __restrict__ kl_g,
                  const __nv_bfloat16* __restrict__ vh_g, const __nv_bfloat16* __restrict__ vl_g,
                  const int* __restrict__ mask, float* __restrict__ Sraw,
                  float2* __restrict__ ml,
                  __nv_bfloat16* __restrict__ ctx_h, __nv_bfloat16* __restrict__ ctx_l)
{
    extern __shared__ __nv_bfloat16 sm_[];
    __nv_bfloat16* qh = sm_;
    __nv_bfloat16* ql = qh + 128*ATS;
    __nv_bfloat16* kh = ql + 128*ATS;
    __nv_bfloat16* kl = kh + 128*ATS;
    __nv_bfloat16* vh = kl + 128*ATS;
    __nv_bfloat16* vl = vh + 128*ATS;
    int* msk = (int*)(vl + 128*ATS);

    const int t0 = blockIdx.x * 128, h = blockIdx.y, b = blockIdx.z;
    const int tid = threadIdx.x, wid = tid >> 5, lane = tid & 31;
    const int qrow = lane >> 2, qc2 = (lane & 3) * 2;
    const int g_row = (lane & 7) + ((lane >> 3) & 1) * 8;
    const int g_col = ((lane >> 4) & 1) * 8;

    const uint32_t uqh = smem_u32(qh), uql = smem_u32(ql);
    const uint32_t ukh = smem_u32(kh), ukl = smem_u32(kl);
    const uint32_t uvh = smem_u32(vh), uvl = smem_u32(vl);

    // per-thread tile-copy geometry: idx = tid + i*256; row=idx>>3, c16=idx&7
    const int lrow0 = tid >> 3, lc16 = tid & 7;
    const size_t gq  = ((size_t)(b*Tq + t0)) * Dq + h*DHq;
    const size_t gkv = ((size_t)(b*Tq)) * Dq + h*DHq;

    // load q tiles (persistent)
    #pragma unroll
    for (int i = 0; i < 4; i++) {
        int row = lrow0 + i*32;
        size_t src = gq + (size_t)row * Dq + lc16*8;
        int dst = row*ATS + lc16*8;
        *(uint4*)&qh[dst] = *(const uint4*)&qh_g[src];
        *(uint4*)&ql[dst] = *(const uint4*)&ql_g[src];
    }
    for (int s = tid; s < Tq; s += 256) msk[s] = mask[b*Tq + s];

    float m0 = -1e30f, m1 = -1e30f, l0 = 0.f, l1 = 0.f;
    float cacc[8][4];
    #pragma unroll
    for (int nf = 0; nf < 8; nf++) {
        cacc[nf][0] = 0.f; cacc[nf][1] = 0.f; cacc[nf][2] = 0.f; cacc[nf][3] = 0.f;
    }

    const size_t prow0 = ((size_t)((b*Hq + h)*Tq) + t0 + wid*16 + qrow) * Tq;

    // prefetch k chunk 0
    uint4 kpf[8], vpf[8];
    #pragma unroll
    for (int i = 0; i < 4; i++) {
        int row = lrow0 + i*32;
        size_t src = gkv + (size_t)row * Dq + lc16*8;
        kpf[i]   = *(const uint4*)&kh_g[src];
        kpf[4+i] = *(const uint4*)&kl_g[src];
    }

    for (int st = 0; st < 8; st++) {
        // store k chunk
        #pragma unroll
        for (int i = 0; i < 4; i++) {
            int dst = (lrow0 + i*32)*ATS + lc16*8;
            *(uint4*)&kh[dst] = kpf[i];
            *(uint4*)&kl[dst] = kpf[4+i];
        }
        __syncthreads();

        // issue v loads (consumed after s_mma)
        #pragma unroll
        for (int i = 0; i < 4; i++) {
            int row = lrow0 + i*32;
            size_t src = gkv + (size_t)(st*128 + row) * Dq + lc16*8;
            vpf[i]   = *(const uint4*)&vh_g[src];
            vpf[4+i] = *(const uint4*)&vl_g[src];
        }

        float acc[16][4];
        s_mma(uqh, uql, ukh, ukl, wid, g_row, g_col, acc);

        // ---- online softmax + raw-S store + P fragments ----
        int s0 = st * 128;
        float cm0 = -1e30f, cm1 = -1e30f;
        #pragma unroll
        for (int nf = 0; nf < 16; nf++) {
            int col = s0 + nf*8 + qc2;
            int k0 = msk[col], k1 = msk[col + 1];
            acc[nf][0] = k0 ? acc[nf][0] : -1e9f;
            acc[nf][1] = k1 ? acc[nf][1] : -1e9f;
            acc[nf][2] = k0 ? acc[nf][2] : -1e9f;
            acc[nf][3] = k1 ? acc[nf][3] : -1e9f;
            cm0 = fmaxf(cm0, fmaxf(acc[nf][0], acc[nf][1]));
            cm1 = fmaxf(cm1, fmaxf(acc[nf][2], acc[nf][3]));
        }
        cm0 = fmaxf(cm0, __shfl_xor_sync(0xffffffffu, cm0, 1));
        cm0 = fmaxf(cm0, __shfl_xor_sync(0xffffffffu, cm0, 2));
        cm1 = fmaxf(cm1, __shfl_xor_sync(0xffffffffu, cm1, 1));
        cm1 = fmaxf(cm1, __shfl_xor_sync(0xffffffffu, cm1, 2));
        float nm0 = fmaxf(m0, cm0), nm1 = fmaxf(m1, cm1);
        float r0 = __expf(m0 - nm0), r1 = __expf(m1 - nm1);
        #pragma unroll
        for (int nf = 0; nf < 8; nf++) {
            cacc[nf][0] *= r0; cacc[nf][1] *= r0;
            cacc[nf][2] *= r1; cacc[nf][3] *= r1;
        }

        float sa0 = 0.f, sa1 = 0.f;
        uint32_t aPh[8][4], aPl[8][4];
        #pragma unroll
        for (int j = 0; j < 8; j++) {
            float p[8];
            #pragma unroll
            for (int u = 0; u < 2; u++) {
                int nf = 2*j + u;
                int col = s0 + nf*8 + qc2;
                *(float2*)&Sraw[prow0 + col]        = make_float2(acc[nf][0], acc[nf][1]);
                *(float2*)&Sraw[prow0 + 8*Tq + col] = make_float2(acc[nf][2], acc[nf][3]);
                float p0 = __expf(acc[nf][0] - nm0);
                float p1 = __expf(acc[nf][1] - nm0);
                float p2 = __expf(acc[nf][2] - nm1);
                float p3 = __expf(acc[nf][3] - nm1);
                sa0 += p0 + p1;  sa1 += p2 + p3;
                p[u*4+0] = p0; p[u*4+1] = p1; p[u*4+2] = p2; p[u*4+3] = p3;
            }
            float h0 = __bfloat162float(__float2bfloat16_rn(p[0]));
            float h1 = __bfloat162float(__float2bfloat16_rn(p[1]));
            float h2 = __bfloat162float(__float2bfloat16_rn(p[2]));
            float h3 = __bfloat162float(__float2bfloat16_rn(p[3]));
            float h4 = __bfloat162float(__float2bfloat16_rn(p[4]));
            float h5 = __bfloat162float(__float2bfloat16_rn(p[5]));
            float h6 = __bfloat162float(__float2bfloat16_rn(p[6]));
            float h7 = __bfloat162float(__float2bfloat16_rn(p[7]));
            aPh[j][0] = bf2x(h0, h1);            aPh[j][1] = bf2x(h2, h3);
            aPh[j][2] = bf2x(h4, h5);            aPh[j][3] = bf2x(h6, h7);
            aPl[j][0] = bf2x(p[0]-h0, p[1]-h1);  aPl[j][1] = bf2x(p[2]-h2, p[3]-h3);
            aPl[j][2] = bf2x(p[4]-h4, p[5]-h5);  aPl[j][3] = bf2x(p[6]-h6, p[7]-h7);
        }
        sa0 += __shfl_xor_sync(0xffffffffu, sa0, 1);
        sa0 += __shfl_xor_sync(0xffffffffu, sa0, 2);
        sa1 += __shfl_xor_sync(0xffffffffu, sa1, 1);
        sa1 += __shfl_xor_sync(0xffffffffu, sa1, 2);
        l0 = l0 * r0 + sa0;  m0 = nm0;
        l1 = l1 * r1 + sa1;  m1 = nm1;

        // store v chunk; prefetch next k
        #pragma unroll
        for (int i = 0; i < 4; i++) {
            int dst = (lrow0 + i*32)*ATS + lc16*8;
            *(uint4*)&vh[dst] = vpf[i];
            *(uint4*)&vl[dst] = vpf[4+i];
        }
        if (st < 7) {
            #pragma unroll
            for (int i = 0; i < 4; i++) {
                int row = lrow0 + i*32;
                size_t src = gkv + (size_t)((st+1)*128 + row) * Dq + lc16*8;
                kpf[i]   = *(const uint4*)&kh_g[src];
                kpf[4+i] = *(const uint4*)&kl_g[src];
            }
        }
        __syncthreads();

        // ctx += P @ V
        #pragma unroll
        for (int ks = 0; ks < 8; ks++) {
            uint32_t bh[8][2], bl[8][2];
            #pragma unroll
            for (int npv = 0; npv < 4; npv++) {
                uint32_t off = (uint32_t)(((ks*16 + g_row) * ATS + npv*16 + g_col) * 2);
                uint32_t r0v, r1v, r2v, r3v;
                LDSM_T_X4(r0v, r1v, r2v, r3v, uvh + off);
                bh[2*npv][0] = r0v;   bh[2*npv][1] = r1v;
                bh[2*npv+1][0] = r2v; bh[2*npv+1][1] = r3v;
                LDSM_T_X4(r0v, r1v, r2v, r3v, uvl + off);
                bl[2*npv][0] = r0v;   bl[2*npv][1] = r1v;
                bl[2*npv+1][0] = r2v; bl[2*npv+1][1] = r3v;
            }
            #pragma unroll
            for (int nf = 0; nf < 8; nf++) {
                MMA16816(cacc[nf], aPh[ks], bh[nf]);
                MMA16816(cacc[nf], aPh[ks], bl[nf]);
                MMA16816(cacc[nf], aPl[ks], bh[nf]);
            }
        }
        __syncthreads();
    }

    const float iL0 = 1.0f / l0, iL1 = 1.0f / l1;

    // per-row stats for the normalize pass (one writer per row)
    if ((lane & 3) == 0) {
        size_t pr = (size_t)(b*Hq + h)*Tq + t0 + wid*16 + qrow;
        ml[pr]     = make_float2(m0, iL0);
        ml[pr + 8] = make_float2(m1, iL1);
    }

    // write ctx as bf16 hi/lo split
    {
        int r = t0 + wid*16 + qrow;
        size_t base0 = ((size_t)(b*Tq + r)) * Dq + h*DHq;
        size_t base1 = ((size_t)(b*Tq + r + 8)) * Dq + h*DHq;
        #pragma unroll
        for (int nf = 0; nf < 8; nf++) {
            int col = nf*8 + qc2;
            float f0 = cacc[nf][0] * iL0, f1 = cacc[nf][1] * iL0;
            float f2 = cacc[nf][2] * iL1, f3 = cacc[nf][3] * iL1;
            float h0 = __bfloat162float(__float2bfloat16_rn(f0));
            float h1 = __bfloat162float(__float2bfloat16_rn(f1));
            float h2 = __bfloat162float(__float2bfloat16_rn(f2));
            float h3 = __bfloat162float(__float2bfloat16_rn(f3));
            *(uint32_t*)&ctx_h[base0 + col] = bf2x(h0, h1);
            *(uint32_t*)&ctx_l[base0 + col] = bf2x(f0 - h0, f1 - h1);
            *(uint32_t*)&ctx_h[base1 + col] = bf2x(h2, h3);
            *(uint32_t*)&ctx_l[base1 + col] = bf2x(f2 - h2, f3 - h3);
        }
    }
}

#define ATTN_SMEM (6*128*ATS*2 + Tq*4)

// probs[row][:] = exp(S - M) * iL   (streaming, in place)
__global__ __launch_bounds__(256)
void probs_norm_kernel(float* __restrict__ probs, const float2* __restrict__ ml)
{
    size_t row = blockIdx.x;
    float2 s = ml[row];
    float4* p = (float4*)(probs + row * Tq);
    float4 v = p[threadIdx.x];
    v.x = __expf(v.x - s.x) * s.y;
    v.y = __expf(v.y - s.x) * s.y;
    v.z = __expf(v.z - s.x) * s.y;
    v.w = __expf(v.w - s.x) * s.y;
    p[threadIdx.x] = v;
}

// ---------------------------------------------------------------------------
extern "C" void kernel_launch(void* const* d_in, const int* in_sizes, int n_in,
                              void* d_out, int out_size)
{
    const float* query   = (const float*)d_in[0];
    const float* key     = (const float*)d_in[1];
    const float* value   = (const float*)d_in[2];
    const float* rel_pos = (const float*)d_in[3];
    const int*   kpm     = (const int*)  d_in[4];
    const float* qn_g = (const float*)d_in[5];
    const float* qn_b = (const float*)d_in[6];
    const float* kn_g = (const float*)d_in[7];
    const float* kn_b = (const float*)d_in[8];
    const float* vn_g = (const float*)d_in[9];
    const float* vn_b = (const float*)d_in[10];
    const float* Wq = (const float*)d_in[11];
    const float* bq = (const float*)d_in[12];
    const float* Wk = (const float*)d_in[13];
    const float* bk = (const float*)d_in[14];
    const float* Wv = (const float*)d_in[15];
    const float* bv = (const float*)d_in[16];
    const float* Wr = (const float*)d_in[17];
    const float* Wo = (const float*)d_in[18];
    const float* bo = (const float*)d_in[19];

    float* out   = (float*)d_out;
    float* probs = out + OUT_ELEMS;

    float* p_k;   cudaGetSymbolAddress((void**)&p_k, g_k);
    float2* p_ml; cudaGetSymbolAddress((void**)&p_ml, g_ml);

    __nv_bfloat16 *lnq_h,*lnq_l,*lnk_h,*lnk_l,*lnv_h,*lnv_l,*rp_h,*rp_l;
    __nv_bfloat16 *qs_h,*qs_l,*kr_h,*kr_l,*vs_h,*vs_l,*ctx_h,*ctx_l;
    __nv_bfloat16 *wq_h,*wq_l,*wk_h,*wk_l,*wv_h,*wv_l,*wr_h,*wr_l,*wo_h,*wo_l;
    cudaGetSymbolAddress((void**)&lnq_h, g_lnq_h); cudaGetSymbolAddress((void**)&lnq_l, g_lnq_l);
    cudaGetSymbolAddress((void**)&lnk_h, g_lnk_h); cudaGetSymbolAddress((void**)&lnk_l, g_lnk_l);
    cudaGetSymbolAddress((void**)&lnv_h, g_lnv_h); cudaGetSymbolAddress((void**)&lnv_l, g_lnv_l);
    cudaGetSymbolAddress((void**)&rp_h,  g_rp_h);  cudaGetSymbolAddress((void**)&rp_l,  g_rp_l);
    cudaGetSymbolAddress((void**)&qs_h,  g_qs_h);  cudaGetSymbolAddress((void**)&qs_l,  g_qs_l);
    cudaGetSymbolAddress((void**)&kr_h,  g_kr_h);  cudaGetSymbolAddress((void**)&kr_l,  g_kr_l);
    cudaGetSymbolAddress((void**)&vs_h,  g_vs_h);  cudaGetSymbolAddress((void**)&vs_l,  g_vs_l);
    cudaGetSymbolAddress((void**)&ctx_h, g_ctx_h); cudaGetSymbolAddress((void**)&ctx_l, g_ctx_l);
    cudaGetSymbolAddress((void**)&wq_h, g_wq_h);   cudaGetSymbolAddress((void**)&wq_l, g_wq_l);
    cudaGetSymbolAddress((void**)&wk_h, g_wk_h);   cudaGetSymbolAddress((void**)&wk_l, g_wk_l);
    cudaGetSymbolAddress((void**)&wv_h, g_wv_h);   cudaGetSymbolAddress((void**)&wv_l, g_wv_l);
    cudaGetSymbolAddress((void**)&wr_h, g_wr_h);   cudaGetSymbolAddress((void**)&wr_l, g_wr_l);
    cudaGetSymbolAddress((void**)&wo_h, g_wo_h);   cudaGetSymbolAddress((void**)&wo_l, g_wo_l);

    cudaFuncSetAttribute(mma_gemm_kernel, cudaFuncAttributeMaxDynamicSharedMemorySize, GSM_BYTES);
    cudaFuncSetAttribute(attn4_kernel, cudaFuncAttributeMaxDynamicSharedMemorySize, ATTN_SMEM);

    // 1) weight transpose + split (one launch)
    WSplitArgs wa;
    wa.W[0]=Wq; wa.H[0]=wq_h; wa.L[0]=wq_l;
    wa.W[1]=Wk; wa.H[1]=wk_h; wa.L[1]=wk_l;
    wa.W[2]=Wv; wa.H[2]=wv_h; wa.L[2]=wv_l;
    wa.W[3]=Wr; wa.H[3]=wr_h; wa.L[3]=wr_l;
    wa.W[4]=Wo; wa.H[4]=wo_h; wa.L[4]=wo_l;
    dim3 wgrid(Dq/32, Dq/32, 5);
    wsplit5_kernel<<<wgrid, 256>>>(wa);

    // 2) LayerNorms with bf16 split output + rel_pos split
    ln_split_kernel<<<Mrows, 256>>>(query, qn_g, qn_b, lnq_h, lnq_l);
    ln_split_kernel<<<Mrows, 256>>>(key,   kn_g, kn_b, lnk_h, lnk_l);
    ln_split_kernel<<<Mrows, 256>>>(value, vn_g, vn_b, lnv_h, lnv_l);
    fsplit_kernel<<<(Mrows*Dq)/1024, 256>>>(rel_pos, rp_h, rp_l);

    // 3) projection GEMMs — q/v/kr written directly as bf16 splits
    dim3 ggrid(Dq/128, Mrows/128);
    mma_gemm_kernel<<<ggrid, 256, GSM_BYTES>>>(lnq_h, lnq_l, wq_h, wq_l, bq, nullptr, 0.125f,
                                               nullptr, qs_h, qs_l, Mrows, Dq, Dq);
    mma_gemm_kernel<<<ggrid, 256, GSM_BYTES>>>(lnk_h, lnk_l, wk_h, wk_l, bk, nullptr, 1.0f,
                                               p_k, nullptr, nullptr, Mrows, Dq, Dq);
    mma_gemm_kernel<<<ggrid, 256, GSM_BYTES>>>(lnv_h, lnv_l, wv_h, wv_l, bv, nullptr, 1.0f,
                                               nullptr, vs_h, vs_l, Mrows, Dq, Dq);
    mma_gemm_kernel<<<ggrid, 256, GSM_BYTES>>>(rp_h,  rp_l,  wr_h, wr_l, nullptr, p_k, 0.1f,
                                               nullptr, kr_h, kr_l, Mrows, Dq, Dq);

    // 4) single-pass flash attention -> raw S + (M,1/L) + bf16-split ctx
    dim3 agrid(Tq/128, Hq, Bq);
    attn4_kernel<<<agrid, 256, ATTN_SMEM>>>(qs_h, qs_l, kr_h, kr_l, vs_h, vs_l,
                                            kpm, probs, p_ml, ctx_h, ctx_l);

    // 5) normalize probs in place
    probs_norm_kernel<<<Bq*Hq*Tq, 256>>>(probs, p_ml);

    // 6) out = ctx@Wo + bo
    mma_gemm_kernel<<<ggrid, 256, GSM_BYTES>>>(ctx_h, ctx_l, wo_h, wo_l, bo, nullptr, 1.0f,
                                               out, nullptr, nullptr, Mrows, Dq, Dq);
}